// round 1
// baseline (speedup 1.0000x reference)
#include <cuda_runtime.h>
#include <math.h>

// ---------------------------------------------------------------------------
// Problem constants (fixed by the dataset)
// ---------------------------------------------------------------------------
#define N_NODES 50000
#define E_EDGES 800000
#define IN_F    256
#define H       4
#define D       64
#define HD      256     // H*D
#define N_ETYPE 8
#define ALPHA   100.0f
#define SLOPE_ATTN 0.2f
#define SLOPE_EW   0.01f

// ---------------------------------------------------------------------------
// Scratch (device globals: no allocation allowed)
// ---------------------------------------------------------------------------
__device__ float    g_ft[N_NODES * HD];      // 51.2 MB : projected features
__device__ float    g_el[N_NODES * H];
__device__ float    g_er[N_NODES * H];
__device__ float    g_e [E_EDGES * H];       // 12.8 MB : per-edge logits, then exp()
__device__ unsigned g_emax[N_NODES * H];     // float-ordered keys for segment max
__device__ float    g_denom[N_NODES * H];

// ---------------------------------------------------------------------------
// float <-> monotonic unsigned key (total order matches float order)
// ---------------------------------------------------------------------------
__device__ __forceinline__ unsigned fkey(float f) {
    unsigned b = __float_as_uint(f);
    return (b & 0x80000000u) ? ~b : (b | 0x80000000u);
}
__device__ __forceinline__ float fdecode(unsigned k) {
    unsigned b = (k & 0x80000000u) ? (k ^ 0x80000000u) : ~k;
    return __uint_as_float(b);
}
__device__ __forceinline__ float lrelu(float x, float s) {
    return x >= 0.0f ? x : s * x;
}

// ---------------------------------------------------------------------------
// K0: init output + reduction scratch
// ---------------------------------------------------------------------------
__global__ void k_init(float* __restrict__ out) {
    int i = blockIdx.x * blockDim.x + threadIdx.x;
    int stride = gridDim.x * blockDim.x;
    for (int j = i; j < N_NODES * HD; j += stride) out[j] = 0.0f;
    for (int j = i; j < N_NODES * H; j += stride) {
        g_emax[j]  = 0u;       // below key(-FLT_MAX)
        g_denom[j] = 0.0f;
    }
}

// ---------------------------------------------------------------------------
// K1: ft = feat @ fc_w^T   (M=50000, N=256, K=256) fp32 SIMT tiled GEMM
//     BM=128, BN=128, BK=16, 256 threads, 8x8 per-thread tile
// ---------------------------------------------------------------------------
#define BM 128
#define BN 128
#define BK 16

__global__ __launch_bounds__(256, 2) void k_gemm(const float* __restrict__ A,
                                                 const float* __restrict__ W) {
    __shared__ float As[BK][BM + 4];
    __shared__ float Bs[BK][BN + 4];

    const int bm  = blockIdx.x * BM;
    const int bn  = blockIdx.y * BN;           // 0 or 128
    const int tid = threadIdx.x;
    const int ty  = tid >> 4;                  // 0..15
    const int tx  = tid & 15;                  // 0..15

    float c[8][8];
#pragma unroll
    for (int i = 0; i < 8; i++)
#pragma unroll
        for (int j = 0; j < 8; j++) c[i][j] = 0.0f;

    for (int k0 = 0; k0 < IN_F; k0 += BK) {
        // load A tile: 128 rows x 16 cols = 512 float4, 2 per thread
#pragma unroll
        for (int l = 0; l < 2; l++) {
            int idx = tid + l * 256;           // 0..511
            int row = idx >> 2;                // 0..127
            int k4  = (idx & 3) * 4;
            int gr  = bm + row;
            float4 v = make_float4(0.f, 0.f, 0.f, 0.f);
            if (gr < N_NODES)
                v = *(const float4*)&A[(long)gr * IN_F + k0 + k4];
            As[k4 + 0][row] = v.x;
            As[k4 + 1][row] = v.y;
            As[k4 + 2][row] = v.z;
            As[k4 + 3][row] = v.w;
        }
        // load W tile: rows bn..bn+127 (output cols), cols k0..k0+15
#pragma unroll
        for (int l = 0; l < 2; l++) {
            int idx = tid + l * 256;
            int row = idx >> 2;
            int k4  = (idx & 3) * 4;
            float4 v = *(const float4*)&W[(bn + row) * IN_F + k0 + k4];
            Bs[k4 + 0][row] = v.x;
            Bs[k4 + 1][row] = v.y;
            Bs[k4 + 2][row] = v.z;
            Bs[k4 + 3][row] = v.w;
        }
        __syncthreads();

#pragma unroll
        for (int kk = 0; kk < BK; kk++) {
            float a[8], b[8];
#pragma unroll
            for (int i = 0; i < 8; i++) a[i] = As[kk][ty * 8 + i];
#pragma unroll
            for (int j = 0; j < 8; j++) b[j] = Bs[kk][tx * 8 + j];
#pragma unroll
            for (int i = 0; i < 8; i++)
#pragma unroll
                for (int j = 0; j < 8; j++) c[i][j] = fmaf(a[i], b[j], c[i][j]);
        }
        __syncthreads();
    }

#pragma unroll
    for (int i = 0; i < 8; i++) {
        int gr = bm + ty * 8 + i;
        if (gr < N_NODES) {
#pragma unroll
            for (int j = 0; j < 8; j += 4) {
                float4 v = make_float4(c[i][j], c[i][j + 1], c[i][j + 2], c[i][j + 3]);
                *(float4*)&g_ft[(long)gr * HD + bn + tx * 8 + j] = v;
            }
        }
    }
}

// ---------------------------------------------------------------------------
// K2: el/er = <ft[n,h,:], attn_l/r[h,:]>   one warp per (n,h)
// ---------------------------------------------------------------------------
__global__ __launch_bounds__(256) void k_elr(const float* __restrict__ attn_l,
                                             const float* __restrict__ attn_r) {
    int w    = (blockIdx.x * blockDim.x + threadIdx.x) >> 5;
    int lane = threadIdx.x & 31;
    if (w >= N_NODES * H) return;
    int n = w >> 2, h = w & 3;
    const float* f = &g_ft[(long)n * HD + h * D];
    float sl = 0.f, sr = 0.f;
#pragma unroll
    for (int d = lane; d < D; d += 32) {
        float v = f[d];
        sl = fmaf(v, attn_l[h * D + d], sl);
        sr = fmaf(v, attn_r[h * D + d], sr);
    }
#pragma unroll
    for (int o = 16; o > 0; o >>= 1) {
        sl += __shfl_down_sync(0xffffffffu, sl, o);
        sr += __shfl_down_sync(0xffffffffu, sr, o);
    }
    if (lane == 0) { g_el[w] = sl; g_er[w] = sr; }
}

// ---------------------------------------------------------------------------
// K3: per-edge logits e = lrelu((el[src]+er[dst])*ew, 0.2), segment max by dst
// ---------------------------------------------------------------------------
__global__ __launch_bounds__(256) void k_edge_logit(const int* __restrict__ src,
                                                    const int* __restrict__ dst,
                                                    const int* __restrict__ etype,
                                                    const float* __restrict__ edge_weight) {
    int e = blockIdx.x * blockDim.x + threadIdx.x;
    if (e >= E_EDGES) return;
    int s = src[e], d = dst[e], t = etype[e] - 1;
    float4 elv = *(const float4*)&g_el[s * H];
    float4 erv = *(const float4*)&g_er[d * H];
    float ve[4];
    float el4[4] = {elv.x, elv.y, elv.z, elv.w};
    float er4[4] = {erv.x, erv.y, erv.z, erv.w};
#pragma unroll
    for (int h = 0; h < H; h++) {
        float w = lrelu(edge_weight[t * H + h] * ALPHA, SLOPE_EW);
        float v = lrelu((el4[h] + er4[h]) * w, SLOPE_ATTN);
        ve[h] = v;
        atomicMax(&g_emax[d * H + h], fkey(v));
    }
    *(float4*)&g_e[e * H] = make_float4(ve[0], ve[1], ve[2], ve[3]);
}

// ---------------------------------------------------------------------------
// K4: ex = exp(e - emax[dst]); denom[dst] += ex   (overwrite g_e with ex)
// ---------------------------------------------------------------------------
__global__ __launch_bounds__(256) void k_edge_exp(const int* __restrict__ dst) {
    int e = blockIdx.x * blockDim.x + threadIdx.x;
    if (e >= E_EDGES) return;
    int d = dst[e];
    float4 ev = *(const float4*)&g_e[e * H];
    float v4[4] = {ev.x, ev.y, ev.z, ev.w};
#pragma unroll
    for (int h = 0; h < H; h++) {
        float m = fdecode(g_emax[d * H + h]);
        float x = expf(v4[h] - m);
        v4[h] = x;
        atomicAdd(&g_denom[d * H + h], x);
    }
    *(float4*)&g_e[e * H] = make_float4(v4[0], v4[1], v4[2], v4[3]);
}

// ---------------------------------------------------------------------------
// K5: scatter: out[dst, h, d] += ex * ft[src, h, d]
//     one block (256 threads == one full [H,D] row) per edge iteration
// ---------------------------------------------------------------------------
#define SC_EPB 8
__global__ __launch_bounds__(256) void k_scatter(const int* __restrict__ src,
                                                 const int* __restrict__ dst,
                                                 float* __restrict__ out) {
    int t = threadIdx.x;           // t = h*64 + d
    int h = t >> 6;
    int e0 = blockIdx.x * SC_EPB;
#pragma unroll
    for (int i = 0; i < SC_EPB; i++) {
        int e = e0 + i;
        if (e >= E_EDGES) return;
        int s = __ldg(&src[e]);
        int d = __ldg(&dst[e]);
        float a = __ldg(&g_e[e * H + h]);
        float v = a * __ldg(&g_ft[(long)s * HD + t]);
        atomicAdd(&out[(long)d * HD + t], v);
    }
}

// ---------------------------------------------------------------------------
// K6: normalize by denom
// ---------------------------------------------------------------------------
__global__ __launch_bounds__(256) void k_norm(float* __restrict__ out) {
    int i = blockIdx.x * 256 + threadIdx.x;        // over N*HD
    int n = i >> 8;
    int h = (i >> 6) & 3;
    float den = g_denom[n * H + h];
    if (den > 0.0f) out[i] *= (1.0f / den);
}

// ---------------------------------------------------------------------------
// launch
// ---------------------------------------------------------------------------
extern "C" void kernel_launch(void* const* d_in, const int* in_sizes, int n_in,
                              void* d_out, int out_size) {
    const float* feat        = (const float*)d_in[0];
    const int*   src         = (const int*)  d_in[1];
    const int*   dst         = (const int*)  d_in[2];
    const int*   edge_feats  = (const int*)  d_in[3];
    const float* fc_w        = (const float*)d_in[4];
    const float* attn_l      = (const float*)d_in[5];
    const float* attn_r      = (const float*)d_in[6];
    const float* edge_weight = (const float*)d_in[7];
    float* out = (float*)d_out;

    k_init<<<1024, 256>>>(out);

    dim3 gemm_grid((N_NODES + BM - 1) / BM, HD / BN);   // (391, 2)
    k_gemm<<<gemm_grid, 256>>>(feat, fc_w);

    k_elr<<<(N_NODES * H + 7) / 8, 256>>>(attn_l, attn_r);          // 8 warps/block

    k_edge_logit<<<(E_EDGES + 255) / 256, 256>>>(src, dst, edge_feats, edge_weight);
    k_edge_exp<<<(E_EDGES + 255) / 256, 256>>>(dst);

    k_scatter<<<(E_EDGES + SC_EPB - 1) / SC_EPB, 256>>>(src, dst, out);

    k_norm<<<(N_NODES * HD) / 256, 256>>>(out);
}

// round 2
// speedup vs baseline: 1.0017x; 1.0017x over previous
#include <cuda_runtime.h>
#include <math.h>

// ---------------------------------------------------------------------------
// Problem constants (fixed by the dataset)
// ---------------------------------------------------------------------------
#define N_NODES 50000
#define E_EDGES 800000
#define IN_F    256
#define H       4
#define D       64
#define HD      256     // H*D
#define N_ETYPE 8
#define ALPHA   100.0f
#define SLOPE_ATTN 0.2f
#define SLOPE_EW   0.01f

// ---------------------------------------------------------------------------
// Scratch (device globals: no allocation allowed)
// ---------------------------------------------------------------------------
__device__ float    g_ft[N_NODES * HD];      // 51.2 MB : projected features
__device__ float    g_el[N_NODES * H];
__device__ float    g_er[N_NODES * H];
__device__ float    g_e [E_EDGES * H];       // 12.8 MB : per-edge logits, then exp()
__device__ unsigned g_emax[N_NODES * H];     // float-ordered keys for segment max
__device__ float    g_denom[N_NODES * H];

// ---------------------------------------------------------------------------
// float <-> monotonic unsigned key (total order matches float order)
// ---------------------------------------------------------------------------
__device__ __forceinline__ unsigned fkey(float f) {
    unsigned b = __float_as_uint(f);
    return (b & 0x80000000u) ? ~b : (b | 0x80000000u);
}
__device__ __forceinline__ float fdecode(unsigned k) {
    unsigned b = (k & 0x80000000u) ? (k ^ 0x80000000u) : ~k;
    return __uint_as_float(b);
}
__device__ __forceinline__ float lrelu(float x, float s) {
    return x >= 0.0f ? x : s * x;
}

// ---------------------------------------------------------------------------
// K0: init output + reduction scratch
// ---------------------------------------------------------------------------
__global__ void k_init(float* __restrict__ out) {
    int i = blockIdx.x * blockDim.x + threadIdx.x;
    int stride = gridDim.x * blockDim.x;
    for (int j = i; j < N_NODES * HD; j += stride) out[j] = 0.0f;
    for (int j = i; j < N_NODES * H; j += stride) {
        g_emax[j]  = 0u;       // below key(-FLT_MAX)
        g_denom[j] = 0.0f;
    }
}

// ---------------------------------------------------------------------------
// K1: ft = feat @ fc_w^T   (M=50000, N=256, K=256) fp32 SIMT tiled GEMM
//     BM=128, BN=128, BK=16, 256 threads, 8x8 per-thread tile
// ---------------------------------------------------------------------------
#define BM 128
#define BN 128
#define BK 16

__global__ __launch_bounds__(256, 2) void k_gemm(const float* __restrict__ A,
                                                 const float* __restrict__ W) {
    __shared__ float As[BK][BM + 4];
    __shared__ float Bs[BK][BN + 4];

    const int bm  = blockIdx.x * BM;
    const int bn  = blockIdx.y * BN;           // 0 or 128
    const int tid = threadIdx.x;
    const int ty  = tid >> 4;                  // 0..15
    const int tx  = tid & 15;                  // 0..15

    float c[8][8];
#pragma unroll
    for (int i = 0; i < 8; i++)
#pragma unroll
        for (int j = 0; j < 8; j++) c[i][j] = 0.0f;

    for (int k0 = 0; k0 < IN_F; k0 += BK) {
        // load A tile: 128 rows x 16 cols = 512 float4, 2 per thread
#pragma unroll
        for (int l = 0; l < 2; l++) {
            int idx = tid + l * 256;           // 0..511
            int row = idx >> 2;                // 0..127
            int k4  = (idx & 3) * 4;
            int gr  = bm + row;
            float4 v = make_float4(0.f, 0.f, 0.f, 0.f);
            if (gr < N_NODES)
                v = *(const float4*)&A[(long)gr * IN_F + k0 + k4];
            As[k4 + 0][row] = v.x;
            As[k4 + 1][row] = v.y;
            As[k4 + 2][row] = v.z;
            As[k4 + 3][row] = v.w;
        }
        // load W tile: rows bn..bn+127 (output cols), cols k0..k0+15
#pragma unroll
        for (int l = 0; l < 2; l++) {
            int idx = tid + l * 256;
            int row = idx >> 2;
            int k4  = (idx & 3) * 4;
            float4 v = *(const float4*)&W[(bn + row) * IN_F + k0 + k4];
            Bs[k4 + 0][row] = v.x;
            Bs[k4 + 1][row] = v.y;
            Bs[k4 + 2][row] = v.z;
            Bs[k4 + 3][row] = v.w;
        }
        __syncthreads();

#pragma unroll
        for (int kk = 0; kk < BK; kk++) {
            float a[8], b[8];
#pragma unroll
            for (int i = 0; i < 8; i++) a[i] = As[kk][ty * 8 + i];
#pragma unroll
            for (int j = 0; j < 8; j++) b[j] = Bs[kk][tx * 8 + j];
#pragma unroll
            for (int i = 0; i < 8; i++)
#pragma unroll
                for (int j = 0; j < 8; j++) c[i][j] = fmaf(a[i], b[j], c[i][j]);
        }
        __syncthreads();
    }

#pragma unroll
    for (int i = 0; i < 8; i++) {
        int gr = bm + ty * 8 + i;
        if (gr < N_NODES) {
#pragma unroll
            for (int j = 0; j < 8; j += 4) {
                float4 v = make_float4(c[i][j], c[i][j + 1], c[i][j + 2], c[i][j + 3]);
                *(float4*)&g_ft[(long)gr * HD + bn + tx * 8 + j] = v;
            }
        }
    }
}

// ---------------------------------------------------------------------------
// K2: el/er = <ft[n,h,:], attn_l/r[h,:]>   one warp per (n,h)
// ---------------------------------------------------------------------------
__global__ __launch_bounds__(256) void k_elr(const float* __restrict__ attn_l,
                                             const float* __restrict__ attn_r) {
    int w    = (blockIdx.x * blockDim.x + threadIdx.x) >> 5;
    int lane = threadIdx.x & 31;
    if (w >= N_NODES * H) return;
    int n = w >> 2, h = w & 3;
    const float* f = &g_ft[(long)n * HD + h * D];
    float sl = 0.f, sr = 0.f;
#pragma unroll
    for (int d = lane; d < D; d += 32) {
        float v = f[d];
        sl = fmaf(v, attn_l[h * D + d], sl);
        sr = fmaf(v, attn_r[h * D + d], sr);
    }
#pragma unroll
    for (int o = 16; o > 0; o >>= 1) {
        sl += __shfl_down_sync(0xffffffffu, sl, o);
        sr += __shfl_down_sync(0xffffffffu, sr, o);
    }
    if (lane == 0) { g_el[w] = sl; g_er[w] = sr; }
}

// ---------------------------------------------------------------------------
// K3: per-edge logits e = lrelu((el[src]+er[dst])*ew, 0.2), segment max by dst
// ---------------------------------------------------------------------------
__global__ __launch_bounds__(256) void k_edge_logit(const int* __restrict__ src,
                                                    const int* __restrict__ dst,
                                                    const int* __restrict__ etype,
                                                    const float* __restrict__ edge_weight) {
    int e = blockIdx.x * blockDim.x + threadIdx.x;
    if (e >= E_EDGES) return;
    int s = src[e], d = dst[e], t = etype[e] - 1;
    float4 elv = *(const float4*)&g_el[s * H];
    float4 erv = *(const float4*)&g_er[d * H];
    float ve[4];
    float el4[4] = {elv.x, elv.y, elv.z, elv.w};
    float er4[4] = {erv.x, erv.y, erv.z, erv.w};
#pragma unroll
    for (int h = 0; h < H; h++) {
        float w = lrelu(edge_weight[t * H + h] * ALPHA, SLOPE_EW);
        float v = lrelu((el4[h] + er4[h]) * w, SLOPE_ATTN);
        ve[h] = v;
        atomicMax(&g_emax[d * H + h], fkey(v));
    }
    *(float4*)&g_e[e * H] = make_float4(ve[0], ve[1], ve[2], ve[3]);
}

// ---------------------------------------------------------------------------
// K4: ex = exp(e - emax[dst]); denom[dst] += ex   (overwrite g_e with ex)
// ---------------------------------------------------------------------------
__global__ __launch_bounds__(256) void k_edge_exp(const int* __restrict__ dst) {
    int e = blockIdx.x * blockDim.x + threadIdx.x;
    if (e >= E_EDGES) return;
    int d = dst[e];
    float4 ev = *(const float4*)&g_e[e * H];
    float v4[4] = {ev.x, ev.y, ev.z, ev.w};
#pragma unroll
    for (int h = 0; h < H; h++) {
        float m = fdecode(g_emax[d * H + h]);
        float x = expf(v4[h] - m);
        v4[h] = x;
        atomicAdd(&g_denom[d * H + h], x);
    }
    *(float4*)&g_e[e * H] = make_float4(v4[0], v4[1], v4[2], v4[3]);
}

// ---------------------------------------------------------------------------
// K5: scatter: out[dst, h, d] += ex * ft[src, h, d]
//     one block (256 threads == one full [H,D] row) per edge iteration
// ---------------------------------------------------------------------------
#define SC_EPB 8
__global__ __launch_bounds__(256) void k_scatter(const int* __restrict__ src,
                                                 const int* __restrict__ dst,
                                                 float* __restrict__ out) {
    int t = threadIdx.x;           // t = h*64 + d
    int h = t >> 6;
    int e0 = blockIdx.x * SC_EPB;
#pragma unroll
    for (int i = 0; i < SC_EPB; i++) {
        int e = e0 + i;
        if (e >= E_EDGES) return;
        int s = __ldg(&src[e]);
        int d = __ldg(&dst[e]);
        float a = __ldg(&g_e[e * H + h]);
        float v = a * __ldg(&g_ft[(long)s * HD + t]);
        atomicAdd(&out[(long)d * HD + t], v);
    }
}

// ---------------------------------------------------------------------------
// K6: normalize by denom
// ---------------------------------------------------------------------------
__global__ __launch_bounds__(256) void k_norm(float* __restrict__ out) {
    int i = blockIdx.x * 256 + threadIdx.x;        // over N*HD
    int n = i >> 8;
    int h = (i >> 6) & 3;
    float den = g_denom[n * H + h];
    if (den > 0.0f) out[i] *= (1.0f / den);
}

// ---------------------------------------------------------------------------
// launch
// ---------------------------------------------------------------------------
extern "C" void kernel_launch(void* const* d_in, const int* in_sizes, int n_in,
                              void* d_out, int out_size) {
    const float* feat        = (const float*)d_in[0];
    const int*   src         = (const int*)  d_in[1];
    const int*   dst         = (const int*)  d_in[2];
    const int*   edge_feats  = (const int*)  d_in[3];
    const float* fc_w        = (const float*)d_in[4];
    const float* attn_l      = (const float*)d_in[5];
    const float* attn_r      = (const float*)d_in[6];
    const float* edge_weight = (const float*)d_in[7];
    float* out = (float*)d_out;

    k_init<<<1024, 256>>>(out);

    dim3 gemm_grid((N_NODES + BM - 1) / BM, HD / BN);   // (391, 2)
    k_gemm<<<gemm_grid, 256>>>(feat, fc_w);

    k_elr<<<(N_NODES * H + 7) / 8, 256>>>(attn_l, attn_r);          // 8 warps/block

    k_edge_logit<<<(E_EDGES + 255) / 256, 256>>>(src, dst, edge_feats, edge_weight);
    k_edge_exp<<<(E_EDGES + 255) / 256, 256>>>(dst);

    k_scatter<<<(E_EDGES + SC_EPB - 1) / SC_EPB, 256>>>(src, dst, out);

    k_norm<<<(N_NODES * HD) / 256, 256>>>(out);
}

// round 4
// speedup vs baseline: 2.1279x; 2.1243x over previous
#include <cuda_runtime.h>
#include <math.h>
#include <stdint.h>

// ---------------------------------------------------------------------------
// Problem constants (fixed by the dataset)
// ---------------------------------------------------------------------------
#define N_NODES 50000
#define E_EDGES 800000
#define IN_F    256
#define H       4
#define D       64
#define HD      256     // H*D
#define ALPHA   100.0f
#define SLOPE_ATTN 0.2f
#define SLOPE_EW   0.01f

// ---------------------------------------------------------------------------
// Scratch (device globals: no allocation allowed)
// ---------------------------------------------------------------------------
__device__ float  g_ft[N_NODES * HD];       // 51.2 MB : projected features
__device__ float  g_el[N_NODES * H];
__device__ float  g_er[N_NODES * H];
__device__ int    g_deg[N_NODES];
__device__ int    g_off[N_NODES + 1];
__device__ int    g_cur[N_NODES];
__device__ int    g_csrc[E_EDGES];          // CSR: src node per slot
__device__ float4 g_eval[E_EDGES];          // CSR: 4-head logits per slot

__device__ __forceinline__ float lrelu(float x, float s) {
    return x >= 0.0f ? x : s * x;
}
__device__ __forceinline__ uint32_t f2tf32(float f) {
    uint32_t r;
    asm("cvt.rna.tf32.f32 %0, %1;" : "=r"(r) : "f"(f));
    return r;
}

// ---------------------------------------------------------------------------
// K0: zero degree histogram
// ---------------------------------------------------------------------------
__global__ void k_init() {
    int i = blockIdx.x * blockDim.x + threadIdx.x;
    int stride = gridDim.x * blockDim.x;
    for (int j = i; j < N_NODES; j += stride) g_deg[j] = 0;
}

// ---------------------------------------------------------------------------
// K1: ft = feat @ fc_w^T   (M=50000, N=256, K=256)  tf32 tensor-core GEMM
//     Block tile 128x128, BK=32, 256 threads = 8 warps (4 m x 2 n),
//     warp tile 32x64 via m16n8k8 (2 m-tiles x 8 n-tiles x 4 k-steps)
// ---------------------------------------------------------------------------
#define GBM 128
#define GBN 128
#define GBK 32
#define SPAD 36   // 36 mod 32 = 4 -> conflict-free fragment LDS

__global__ __launch_bounds__(256) void k_gemm(const float* __restrict__ A,
                                              const float* __restrict__ W) {
    __shared__ uint32_t As[GBM][SPAD];
    __shared__ uint32_t Bs[GBN][SPAD];

    const int bm   = blockIdx.x * GBM;
    const int bn   = blockIdx.y * GBN;
    const int tid  = threadIdx.x;
    const int wid  = tid >> 5;
    const int lane = tid & 31;
    const int wm   = wid & 3;          // 0..3  -> 32 rows each
    const int wn   = wid >> 2;         // 0..1  -> 64 cols each
    const int g    = lane >> 2;        // group id 0..7
    const int t    = lane & 3;         // thread-in-group 0..3

    float c[2][8][4];
#pragma unroll
    for (int i = 0; i < 2; i++)
#pragma unroll
        for (int j = 0; j < 8; j++)
#pragma unroll
            for (int q = 0; q < 4; q++) c[i][j][q] = 0.0f;

    for (int k0 = 0; k0 < IN_F; k0 += GBK) {
        // load A tile (128x32) and W tile (128x32), converting to tf32
#pragma unroll
        for (int l = 0; l < 4; l++) {
            int fidx = tid + l * 256;      // 0..1023 float4 slots
            int row  = fidx >> 3;          // 0..127
            int col4 = (fidx & 7) * 4;
            int gr   = bm + row;
            float4 va = make_float4(0.f, 0.f, 0.f, 0.f);
            if (gr < N_NODES) va = *(const float4*)&A[(size_t)gr * IN_F + k0 + col4];
            As[row][col4 + 0] = f2tf32(va.x);
            As[row][col4 + 1] = f2tf32(va.y);
            As[row][col4 + 2] = f2tf32(va.z);
            As[row][col4 + 3] = f2tf32(va.w);
            float4 vb = *(const float4*)&W[(size_t)(bn + row) * IN_F + k0 + col4];
            Bs[row][col4 + 0] = f2tf32(vb.x);
            Bs[row][col4 + 1] = f2tf32(vb.y);
            Bs[row][col4 + 2] = f2tf32(vb.z);
            Bs[row][col4 + 3] = f2tf32(vb.w);
        }
        __syncthreads();

#pragma unroll
        for (int ks = 0; ks < 4; ks++) {
            const int k8 = ks * 8;
            uint32_t a[2][4];
#pragma unroll
            for (int i = 0; i < 2; i++) {
                int r0 = wm * 32 + i * 16;
                a[i][0] = As[r0 + g    ][k8 + t    ];
                a[i][1] = As[r0 + g + 8][k8 + t    ];
                a[i][2] = As[r0 + g    ][k8 + t + 4];
                a[i][3] = As[r0 + g + 8][k8 + t + 4];
            }
            uint32_t b[8][2];
#pragma unroll
            for (int j = 0; j < 8; j++) {
                int n0 = wn * 64 + j * 8;
                b[j][0] = Bs[n0 + g][k8 + t    ];
                b[j][1] = Bs[n0 + g][k8 + t + 4];
            }
#pragma unroll
            for (int i = 0; i < 2; i++)
#pragma unroll
                for (int j = 0; j < 8; j++) {
                    asm volatile(
                        "mma.sync.aligned.m16n8k8.row.col.f32.tf32.tf32.f32 "
                        "{%0,%1,%2,%3},{%4,%5,%6,%7},{%8,%9},{%0,%1,%2,%3};"
                        : "+f"(c[i][j][0]), "+f"(c[i][j][1]),
                          "+f"(c[i][j][2]), "+f"(c[i][j][3])
                        : "r"(a[i][0]), "r"(a[i][1]), "r"(a[i][2]), "r"(a[i][3]),
                          "r"(b[j][0]), "r"(b[j][1]));
                }
        }
        __syncthreads();
    }

    // epilogue
#pragma unroll
    for (int i = 0; i < 2; i++) {
        int r0 = bm + wm * 32 + i * 16;
#pragma unroll
        for (int j = 0; j < 8; j++) {
            int col = bn + wn * 64 + j * 8 + t * 2;
            int ra = r0 + g, rb = r0 + g + 8;
            if (ra < N_NODES)
                *(float2*)&g_ft[(size_t)ra * HD + col] = make_float2(c[i][j][0], c[i][j][1]);
            if (rb < N_NODES)
                *(float2*)&g_ft[(size_t)rb * HD + col] = make_float2(c[i][j][2], c[i][j][3]);
        }
    }
}

// ---------------------------------------------------------------------------
// K2: el/er = <ft[n,h,:], attn_l/r[h,:]>   one warp per (n,h)
// ---------------------------------------------------------------------------
__global__ __launch_bounds__(256) void k_elr(const float* __restrict__ attn_l,
                                             const float* __restrict__ attn_r) {
    int w    = (blockIdx.x * blockDim.x + threadIdx.x) >> 5;
    int lane = threadIdx.x & 31;
    if (w >= N_NODES * H) return;
    int n = w >> 2, h = w & 3;
    const float* f = &g_ft[(size_t)n * HD + h * D];
    float sl = 0.f, sr = 0.f;
#pragma unroll
    for (int d = lane; d < D; d += 32) {
        float v = f[d];
        sl = fmaf(v, attn_l[h * D + d], sl);
        sr = fmaf(v, attn_r[h * D + d], sr);
    }
#pragma unroll
    for (int o = 16; o > 0; o >>= 1) {
        sl += __shfl_down_sync(0xffffffffu, sl, o);
        sr += __shfl_down_sync(0xffffffffu, sr, o);
    }
    if (lane == 0) { g_el[w] = sl; g_er[w] = sr; }
}

// ---------------------------------------------------------------------------
// K3: degree histogram over dst
// ---------------------------------------------------------------------------
__global__ __launch_bounds__(256) void k_hist(const int* __restrict__ dst) {
    int e = blockIdx.x * blockDim.x + threadIdx.x;
    if (e < E_EDGES) atomicAdd(&g_deg[dst[e]], 1);
}

// ---------------------------------------------------------------------------
// K4: exclusive prefix sum over g_deg -> g_off (and g_cur).  Single block.
// ---------------------------------------------------------------------------
__global__ __launch_bounds__(1024) void k_scan() {
    __shared__ int wsum[32];
    __shared__ int s_carry;
    int tid  = threadIdx.x;
    int lane = tid & 31;
    int w    = tid >> 5;
    if (tid == 0) s_carry = 0;
    __syncthreads();

    for (int base = 0; base < N_NODES; base += 1024) {
        int idx = base + tid;
        int v = (idx < N_NODES) ? g_deg[idx] : 0;
        int x = v;
#pragma unroll
        for (int o = 1; o < 32; o <<= 1) {
            int y = __shfl_up_sync(0xffffffffu, x, o);
            if (lane >= o) x += y;
        }
        if (lane == 31) wsum[w] = x;
        __syncthreads();
        if (w == 0) {
            int y = wsum[lane];
#pragma unroll
            for (int o = 1; o < 32; o <<= 1) {
                int z = __shfl_up_sync(0xffffffffu, y, o);
                if (lane >= o) y += z;
            }
            wsum[lane] = y;
        }
        __syncthreads();
        int excl = s_carry + (w > 0 ? wsum[w - 1] : 0) + x - v;
        if (idx < N_NODES) { g_off[idx] = excl; g_cur[idx] = excl; }
        __syncthreads();
        if (tid == 0) s_carry += wsum[31];
        __syncthreads();
    }
    if (tid == 0) g_off[N_NODES] = s_carry;
}

// ---------------------------------------------------------------------------
// K5: per-edge logits + scatter into CSR slots
// ---------------------------------------------------------------------------
__global__ __launch_bounds__(256) void k_build(const int* __restrict__ src,
                                               const int* __restrict__ dst,
                                               const int* __restrict__ etype,
                                               const float* __restrict__ edge_weight) {
    int e = blockIdx.x * blockDim.x + threadIdx.x;
    if (e >= E_EDGES) return;
    int s = src[e], d = dst[e], t = etype[e] - 1;
    float4 elv = *(const float4*)&g_el[s * H];
    float4 erv = *(const float4*)&g_er[d * H];
    float el4[4] = {elv.x, elv.y, elv.z, elv.w};
    float er4[4] = {erv.x, erv.y, erv.z, erv.w};
    float ve[4];
#pragma unroll
    for (int h = 0; h < H; h++) {
        float w = lrelu(__ldg(&edge_weight[t * H + h]) * ALPHA, SLOPE_EW);
        ve[h] = lrelu((el4[h] + er4[h]) * w, SLOPE_ATTN);
    }
    int pos = atomicAdd(&g_cur[d], 1);
    g_csrc[pos] = s;
    g_eval[pos] = make_float4(ve[0], ve[1], ve[2], ve[3]);
}

// ---------------------------------------------------------------------------
// K6: fused edge-softmax + weighted aggregate. One warp per dst node.
//     Each lane owns 8 output elements (lane + 32*q), q = 0..7, head = q>>1.
// ---------------------------------------------------------------------------
__global__ __launch_bounds__(256) void k_fused(float* __restrict__ out) {
    __shared__ float4 s_coef[8][32];
    __shared__ int    s_src[8][32];

    int w    = threadIdx.x >> 5;
    int lane = threadIdx.x & 31;
    int n    = blockIdx.x * 8 + w;
    if (n >= N_NODES) return;

    int beg = g_off[n];
    int cnt = g_off[n + 1] - beg;

    if (cnt == 0) {
#pragma unroll
        for (int q = 0; q < 8; q++) out[(size_t)n * HD + q * 32 + lane] = 0.0f;
        return;
    }

    // pass 1: per-head max
    float4 mx = make_float4(-INFINITY, -INFINITY, -INFINITY, -INFINITY);
    for (int i = lane; i < cnt; i += 32) {
        float4 v = g_eval[beg + i];
        mx.x = fmaxf(mx.x, v.x); mx.y = fmaxf(mx.y, v.y);
        mx.z = fmaxf(mx.z, v.z); mx.w = fmaxf(mx.w, v.w);
    }
#pragma unroll
    for (int o = 16; o > 0; o >>= 1) {
        mx.x = fmaxf(mx.x, __shfl_xor_sync(0xffffffffu, mx.x, o));
        mx.y = fmaxf(mx.y, __shfl_xor_sync(0xffffffffu, mx.y, o));
        mx.z = fmaxf(mx.z, __shfl_xor_sync(0xffffffffu, mx.z, o));
        mx.w = fmaxf(mx.w, __shfl_xor_sync(0xffffffffu, mx.w, o));
    }

    // pass 2: exp coefficients + denominator + register-accumulated aggregate
    float acc[8];
#pragma unroll
    for (int q = 0; q < 8; q++) acc[q] = 0.0f;
    float4 den = make_float4(0.f, 0.f, 0.f, 0.f);

    for (int base = 0; base < cnt; base += 32) {
        int i = base + lane;
        int m = min(32, cnt - base);
        if (i < cnt) {
            float4 v = g_eval[beg + i];
            float4 cf;
            cf.x = __expf(v.x - mx.x);
            cf.y = __expf(v.y - mx.y);
            cf.z = __expf(v.z - mx.z);
            cf.w = __expf(v.w - mx.w);
            den.x += cf.x; den.y += cf.y; den.z += cf.z; den.w += cf.w;
            s_coef[w][lane] = cf;
            s_src[w][lane]  = g_csrc[beg + i];
        }
        __syncwarp();
        for (int j = 0; j < m; j++) {
            int sidx = s_src[w][j];
            float4 cf = s_coef[w][j];
            float cfa[4] = {cf.x, cf.y, cf.z, cf.w};
            const float* f = &g_ft[(size_t)sidx * HD];
#pragma unroll
            for (int q = 0; q < 8; q++)
                acc[q] = fmaf(cfa[q >> 1], __ldg(&f[q * 32 + lane]), acc[q]);
        }
        __syncwarp();
    }

    // reduce denominator across warp, normalize, write row once
#pragma unroll
    for (int o = 16; o > 0; o >>= 1) {
        den.x += __shfl_xor_sync(0xffffffffu, den.x, o);
        den.y += __shfl_xor_sync(0xffffffffu, den.y, o);
        den.z += __shfl_xor_sync(0xffffffffu, den.z, o);
        den.w += __shfl_xor_sync(0xffffffffu, den.w, o);
    }
    float rd[4] = {1.0f / den.x, 1.0f / den.y, 1.0f / den.z, 1.0f / den.w};
#pragma unroll
    for (int q = 0; q < 8; q++)
        out[(size_t)n * HD + q * 32 + lane] = acc[q] * rd[q >> 1];
}

// ---------------------------------------------------------------------------
// launch
// ---------------------------------------------------------------------------
extern "C" void kernel_launch(void* const* d_in, const int* in_sizes, int n_in,
                              void* d_out, int out_size) {
    const float* feat        = (const float*)d_in[0];
    const int*   src         = (const int*)  d_in[1];
    const int*   dst         = (const int*)  d_in[2];
    const int*   edge_feats  = (const int*)  d_in[3];
    const float* fc_w        = (const float*)d_in[4];
    const float* attn_l      = (const float*)d_in[5];
    const float* attn_r      = (const float*)d_in[6];
    const float* edge_weight = (const float*)d_in[7];
    float* out = (float*)d_out;

    k_init<<<256, 256>>>();

    dim3 gemm_grid((N_NODES + GBM - 1) / GBM, HD / GBN);   // (391, 2)
    k_gemm<<<gemm_grid, 256>>>(feat, fc_w);

    k_elr<<<(N_NODES * H + 7) / 8, 256>>>(attn_l, attn_r);

    k_hist<<<(E_EDGES + 255) / 256, 256>>>(dst);
    k_scan<<<1, 1024>>>();
    k_build<<<(E_EDGES + 255) / 256, 256>>>(src, dst, edge_feats, edge_weight);

    k_fused<<<N_NODES / 8, 256>>>(out);
}

// round 6
// speedup vs baseline: 3.0089x; 1.4140x over previous
#include <cuda_runtime.h>
#include <cuda_fp16.h>
#include <math.h>
#include <stdint.h>

// ---------------------------------------------------------------------------
// Problem constants (fixed by the dataset)
// ---------------------------------------------------------------------------
#define N_NODES 50000
#define E_EDGES 800000
#define IN_F    256
#define H       4
#define D       64
#define HD      256     // H*D
#define ALPHA   100.0f
#define SLOPE_ATTN 0.2f
#define SLOPE_EW   0.01f

// ---------------------------------------------------------------------------
// Scratch (device globals: no allocation allowed)
// ---------------------------------------------------------------------------
__device__ __half  g_fth[N_NODES * HD];      // 25.6 MB : projected features (half)
__device__ __align__(16) float g_el[N_NODES * H];
__device__ __align__(16) float g_er[N_NODES * H];
__device__ __align__(16) int   g_deg[N_NODES];
__device__ __align__(16) int   g_off[N_NODES + 4];
__device__ __align__(16) int   g_cur[N_NODES];
__device__ int    g_csrc[E_EDGES];           // CSR: src node per slot
__device__ float4 g_eval[E_EDGES];           // CSR: 4-head logits per slot

__device__ __forceinline__ float lrelu(float x, float s) {
    return x >= 0.0f ? x : s * x;
}
__device__ __forceinline__ uint32_t f2tf32(float f) {
    uint32_t r;
    asm("cvt.rna.tf32.f32 %0, %1;" : "=r"(r) : "f"(f));
    return r;
}

// ---------------------------------------------------------------------------
// K0: zero degree histogram + el/er accumulators
// ---------------------------------------------------------------------------
__global__ void k_init() {
    int i = blockIdx.x * blockDim.x + threadIdx.x;
    int stride = gridDim.x * blockDim.x;
    for (int j = i; j < N_NODES; j += stride) g_deg[j] = 0;
    for (int j = i; j < N_NODES * H; j += stride) { g_el[j] = 0.0f; g_er[j] = 0.0f; }
}

// ---------------------------------------------------------------------------
// K1: ft = feat @ fc_w^T   (M=50000, N=256, K=256)  tf32 tensor-core GEMM
//     Epilogue: write half features + accumulate el/er via atomics.
// ---------------------------------------------------------------------------
#define GBM 128
#define GBN 128
#define GBK 32
#define SPAD 36   // 36 mod 32 = 4 -> conflict-free fragment LDS

__global__ __launch_bounds__(256) void k_gemm(const float* __restrict__ A,
                                              const float* __restrict__ W,
                                              const float* __restrict__ attn_l,
                                              const float* __restrict__ attn_r) {
    __shared__ uint32_t As[GBM][SPAD];
    __shared__ uint32_t Bs[GBN][SPAD];

    const int bm   = blockIdx.x * GBM;
    const int bn   = blockIdx.y * GBN;
    const int tid  = threadIdx.x;
    const int wid  = tid >> 5;
    const int lane = tid & 31;
    const int wm   = wid & 3;          // 0..3  -> 32 rows each
    const int wn   = wid >> 2;         // 0..1  -> 64 cols each
    const int g    = lane >> 2;        // group id 0..7
    const int t    = lane & 3;         // thread-in-group 0..3

    float c[2][8][4];
#pragma unroll
    for (int i = 0; i < 2; i++)
#pragma unroll
        for (int j = 0; j < 8; j++)
#pragma unroll
            for (int q = 0; q < 4; q++) c[i][j][q] = 0.0f;

    for (int k0 = 0; k0 < IN_F; k0 += GBK) {
#pragma unroll
        for (int l = 0; l < 4; l++) {
            int fidx = tid + l * 256;      // 0..1023 float4 slots
            int row  = fidx >> 3;          // 0..127
            int col4 = (fidx & 7) * 4;
            int gr   = bm + row;
            float4 va = make_float4(0.f, 0.f, 0.f, 0.f);
            if (gr < N_NODES) va = *(const float4*)&A[(size_t)gr * IN_F + k0 + col4];
            As[row][col4 + 0] = f2tf32(va.x);
            As[row][col4 + 1] = f2tf32(va.y);
            As[row][col4 + 2] = f2tf32(va.z);
            As[row][col4 + 3] = f2tf32(va.w);
            float4 vb = *(const float4*)&W[(size_t)(bn + row) * IN_F + k0 + col4];
            Bs[row][col4 + 0] = f2tf32(vb.x);
            Bs[row][col4 + 1] = f2tf32(vb.y);
            Bs[row][col4 + 2] = f2tf32(vb.z);
            Bs[row][col4 + 3] = f2tf32(vb.w);
        }
        __syncthreads();

#pragma unroll
        for (int ks = 0; ks < 4; ks++) {
            const int k8 = ks * 8;
            uint32_t a[2][4];
#pragma unroll
            for (int i = 0; i < 2; i++) {
                int r0 = wm * 32 + i * 16;
                a[i][0] = As[r0 + g    ][k8 + t    ];
                a[i][1] = As[r0 + g + 8][k8 + t    ];
                a[i][2] = As[r0 + g    ][k8 + t + 4];
                a[i][3] = As[r0 + g + 8][k8 + t + 4];
            }
            uint32_t b[8][2];
#pragma unroll
            for (int j = 0; j < 8; j++) {
                int n0 = wn * 64 + j * 8;
                b[j][0] = Bs[n0 + g][k8 + t    ];
                b[j][1] = Bs[n0 + g][k8 + t + 4];
            }
#pragma unroll
            for (int i = 0; i < 2; i++)
#pragma unroll
                for (int j = 0; j < 8; j++) {
                    asm volatile(
                        "mma.sync.aligned.m16n8k8.row.col.f32.tf32.tf32.f32 "
                        "{%0,%1,%2,%3},{%4,%5,%6,%7},{%8,%9},{%0,%1,%2,%3};"
                        : "+f"(c[i][j][0]), "+f"(c[i][j][1]),
                          "+f"(c[i][j][2]), "+f"(c[i][j][3])
                        : "r"(a[i][0]), "r"(a[i][1]), "r"(a[i][2]), "r"(a[i][3]),
                          "r"(b[j][0]), "r"(b[j][1]));
                }
        }
        __syncthreads();
    }

    // epilogue: each thread's 16 cols live in exactly one head block of 64
    const int h = (bn + wn * 64) >> 6;                // head index 0..3
    const float* al = attn_l + h * D;
    const float* ar = attn_r + h * D;

#pragma unroll
    for (int i = 0; i < 2; i++) {
        int r0 = bm + wm * 32 + i * 16;
        int ra = r0 + g, rb = r0 + g + 8;
        float ela = 0.f, era = 0.f, elb = 0.f, erb = 0.f;
#pragma unroll
        for (int j = 0; j < 8; j++) {
            int dcol = j * 8 + t * 2;                 // col within head (0..62)
            int col  = bn + wn * 64 + dcol;           // global col
            float a0 = __ldg(&al[dcol]), a1 = __ldg(&al[dcol + 1]);
            float b0 = __ldg(&ar[dcol]), b1 = __ldg(&ar[dcol + 1]);
            ela = fmaf(c[i][j][0], a0, fmaf(c[i][j][1], a1, ela));
            era = fmaf(c[i][j][0], b0, fmaf(c[i][j][1], b1, era));
            elb = fmaf(c[i][j][2], a0, fmaf(c[i][j][3], a1, elb));
            erb = fmaf(c[i][j][2], b0, fmaf(c[i][j][3], b1, erb));
            if (ra < N_NODES)
                *(__half2*)&g_fth[(size_t)ra * HD + col] =
                    __float22half2_rn(make_float2(c[i][j][0], c[i][j][1]));
            if (rb < N_NODES)
                *(__half2*)&g_fth[(size_t)rb * HD + col] =
                    __float22half2_rn(make_float2(c[i][j][2], c[i][j][3]));
        }
        if (ra < N_NODES) {
            atomicAdd(&g_el[ra * H + h], ela);
            atomicAdd(&g_er[ra * H + h], era);
        }
        if (rb < N_NODES) {
            atomicAdd(&g_el[rb * H + h], elb);
            atomicAdd(&g_er[rb * H + h], erb);
        }
    }
}

// ---------------------------------------------------------------------------
// K2: degree histogram over dst (int4 vectorized; E divisible by 4)
// ---------------------------------------------------------------------------
__global__ __launch_bounds__(256) void k_hist(const int* __restrict__ dst) {
    int i = blockIdx.x * blockDim.x + threadIdx.x;
    if (i >= E_EDGES / 4) return;
    int4 d = ((const int4*)dst)[i];
    atomicAdd(&g_deg[d.x], 1);
    atomicAdd(&g_deg[d.y], 1);
    atomicAdd(&g_deg[d.z], 1);
    atomicAdd(&g_deg[d.w], 1);
}

// ---------------------------------------------------------------------------
// K3: exclusive prefix sum over g_deg -> g_off, g_cur. Single block, 4x wide.
// ---------------------------------------------------------------------------
#define N4 ((N_NODES + 3) / 4)   // 12500
__global__ __launch_bounds__(1024) void k_scan() {
    __shared__ int wsum[32];
    __shared__ int s_carry;
    int tid  = threadIdx.x;
    int lane = tid & 31;
    int w    = tid >> 5;
    if (tid == 0) s_carry = 0;
    __syncthreads();

    for (int base = 0; base < N4; base += 1024) {
        int i4 = base + tid;
        int4 v = (i4 < N4) ? ((const int4*)g_deg)[i4] : make_int4(0, 0, 0, 0);
        int tot = v.x + v.y + v.z + v.w;
        int x = tot;
#pragma unroll
        for (int o = 1; o < 32; o <<= 1) {
            int y = __shfl_up_sync(0xffffffffu, x, o);
            if (lane >= o) x += y;
        }
        if (lane == 31) wsum[w] = x;
        __syncthreads();
        if (w == 0) {
            int y = wsum[lane];
#pragma unroll
            for (int o = 1; o < 32; o <<= 1) {
                int z = __shfl_up_sync(0xffffffffu, y, o);
                if (lane >= o) y += z;
            }
            wsum[lane] = y;
        }
        __syncthreads();
        if (i4 < N4) {
            int excl = s_carry + (w > 0 ? wsum[w - 1] : 0) + x - tot;
            int4 o4 = make_int4(excl, excl + v.x, excl + v.x + v.y,
                                excl + v.x + v.y + v.z);
            ((int4*)g_off)[i4] = o4;
            ((int4*)g_cur)[i4] = o4;
        }
        __syncthreads();
        if (tid == 0) s_carry += wsum[31];
        __syncthreads();
    }
    if (tid == 0) g_off[N_NODES] = s_carry;
}

// ---------------------------------------------------------------------------
// K4: per-edge logits + scatter into CSR slots
// ---------------------------------------------------------------------------
__global__ __launch_bounds__(256) void k_build(const int* __restrict__ src,
                                               const int* __restrict__ dst,
                                               const int* __restrict__ etype,
                                               const float* __restrict__ edge_weight) {
    int e = blockIdx.x * blockDim.x + threadIdx.x;
    if (e >= E_EDGES) return;
    int s = src[e], d = dst[e], t = etype[e] - 1;
    float4 elv = *(const float4*)&g_el[s * H];
    float4 erv = *(const float4*)&g_er[d * H];
    float el4[4] = {elv.x, elv.y, elv.z, elv.w};
    float er4[4] = {erv.x, erv.y, erv.z, erv.w};
    float ve[4];
#pragma unroll
    for (int h = 0; h < H; h++) {
        float w = lrelu(__ldg(&edge_weight[t * H + h]) * ALPHA, SLOPE_EW);
        ve[h] = lrelu((el4[h] + er4[h]) * w, SLOPE_ATTN);
    }
    int pos = atomicAdd(&g_cur[d], 1);
    g_csrc[pos] = s;
    g_eval[pos] = make_float4(ve[0], ve[1], ve[2], ve[3]);
}

// ---------------------------------------------------------------------------
// K5: fused edge-softmax + weighted aggregate. One warp per dst node.
//     Lane owns 8 CONTIGUOUS output elements [lane*8, lane*8+8) -> one
//     uint4 (8 halves) load per edge; head = lane>>3 is lane-constant.
// ---------------------------------------------------------------------------
__global__ __launch_bounds__(256) void k_fused(float* __restrict__ out) {
    __shared__ float s_cf[8][32 * 4];     // [warp][edge*4 + head]
    __shared__ int   s_src[8][32];

    int w    = threadIdx.x >> 5;
    int lane = threadIdx.x & 31;
    int n    = blockIdx.x * 8 + w;
    if (n >= N_NODES) return;

    int beg = g_off[n];
    int cnt = g_off[n + 1] - beg;

    float* orow = &out[(size_t)n * HD + lane * 8];
    if (cnt == 0) {
        float4 z = make_float4(0.f, 0.f, 0.f, 0.f);
        *(float4*)&orow[0] = z;
        *(float4*)&orow[4] = z;
        return;
    }

    // pass 1: per-head max
    float4 mx = make_float4(-INFINITY, -INFINITY, -INFINITY, -INFINITY);
    for (int i = lane; i < cnt; i += 32) {
        float4 v = g_eval[beg + i];
        mx.x = fmaxf(mx.x, v.x); mx.y = fmaxf(mx.y, v.y);
        mx.z = fmaxf(mx.z, v.z); mx.w = fmaxf(mx.w, v.w);
    }
#pragma unroll
    for (int o = 16; o > 0; o >>= 1) {
        mx.x = fmaxf(mx.x, __shfl_xor_sync(0xffffffffu, mx.x, o));
        mx.y = fmaxf(mx.y, __shfl_xor_sync(0xffffffffu, mx.y, o));
        mx.z = fmaxf(mx.z, __shfl_xor_sync(0xffffffffu, mx.z, o));
        mx.w = fmaxf(mx.w, __shfl_xor_sync(0xffffffffu, mx.w, o));
    }

    // pass 2: exp coefficients + denominator + register-accumulated aggregate
    const int hsel = lane >> 3;
    const uint4* __restrict__ fth = (const uint4*)g_fth;   // 32 uint4 per node

    float acc[8];
#pragma unroll
    for (int q = 0; q < 8; q++) acc[q] = 0.0f;
    float4 den = make_float4(0.f, 0.f, 0.f, 0.f);

    for (int base = 0; base < cnt; base += 32) {
        int i = base + lane;
        int m = min(32, cnt - base);
        if (i < cnt) {
            float4 v = g_eval[beg + i];
            float4 cf;
            cf.x = __expf(v.x - mx.x);
            cf.y = __expf(v.y - mx.y);
            cf.z = __expf(v.z - mx.z);
            cf.w = __expf(v.w - mx.w);
            den.x += cf.x; den.y += cf.y; den.z += cf.z; den.w += cf.w;
            s_cf[w][lane * 4 + 0] = cf.x;
            s_cf[w][lane * 4 + 1] = cf.y;
            s_cf[w][lane * 4 + 2] = cf.z;
            s_cf[w][lane * 4 + 3] = cf.w;
            s_src[w][lane] = g_csrc[beg + i];
        }
        __syncwarp();
        for (int j = 0; j < m; j++) {
            int   sidx = s_src[w][j];
            float cf   = s_cf[w][j * 4 + hsel];
            uint4 hv   = __ldg(&fth[(size_t)sidx * 32 + lane]);
            const __half2* hp = (const __half2*)&hv;
#pragma unroll
            for (int p = 0; p < 4; p++) {
                float2 f2 = __half22float2(hp[p]);
                acc[2 * p + 0] = fmaf(cf, f2.x, acc[2 * p + 0]);
                acc[2 * p + 1] = fmaf(cf, f2.y, acc[2 * p + 1]);
            }
        }
        __syncwarp();
    }

    // reduce denominator across warp, normalize, write row once
#pragma unroll
    for (int o = 16; o > 0; o >>= 1) {
        den.x += __shfl_xor_sync(0xffffffffu, den.x, o);
        den.y += __shfl_xor_sync(0xffffffffu, den.y, o);
        den.z += __shfl_xor_sync(0xffffffffu, den.z, o);
        den.w += __shfl_xor_sync(0xffffffffu, den.w, o);
    }
    float dh[4] = {den.x, den.y, den.z, den.w};
    float rd = 1.0f / dh[hsel];
    float4 o0 = make_float4(acc[0] * rd, acc[1] * rd, acc[2] * rd, acc[3] * rd);
    float4 o1 = make_float4(acc[4] * rd, acc[5] * rd, acc[6] * rd, acc[7] * rd);
    *(float4*)&orow[0] = o0;
    *(float4*)&orow[4] = o1;
}

// ---------------------------------------------------------------------------
// launch
// ---------------------------------------------------------------------------
extern "C" void kernel_launch(void* const* d_in, const int* in_sizes, int n_in,
                              void* d_out, int out_size) {
    const float* feat        = (const float*)d_in[0];
    const int*   src         = (const int*)  d_in[1];
    const int*   dst         = (const int*)  d_in[2];
    const int*   edge_feats  = (const int*)  d_in[3];
    const float* fc_w        = (const float*)d_in[4];
    const float* attn_l      = (const float*)d_in[5];
    const float* attn_r      = (const float*)d_in[6];
    const float* edge_weight = (const float*)d_in[7];
    float* out = (float*)d_out;

    k_init<<<512, 256>>>();

    dim3 gemm_grid((N_NODES + GBM - 1) / GBM, HD / GBN);   // (391, 2)
    k_gemm<<<gemm_grid, 256>>>(feat, fc_w, attn_l, attn_r);

    k_hist<<<(E_EDGES / 4 + 255) / 256, 256>>>(dst);
    k_scan<<<1, 1024>>>();
    k_build<<<(E_EDGES + 255) / 256, 256>>>(src, dst, edge_feats, edge_weight);

    k_fused<<<(N_NODES + 7) / 8, 256>>>(out);
}

// round 8
// speedup vs baseline: 3.4563x; 1.1487x over previous
#include <cuda_runtime.h>
#include <cuda_fp16.h>
#include <math.h>
#include <stdint.h>

// ---------------------------------------------------------------------------
// Problem constants (fixed by the dataset)
// ---------------------------------------------------------------------------
#define N_NODES 50000
#define E_EDGES 800000
#define IN_F    256
#define H       4
#define D       64
#define HD      256     // H*D
#define ALPHA   100.0f
#define SLOPE_ATTN 0.2f
#define SLOPE_EW   0.01f

#define N4      (N_NODES / 4)        // 12500 int4 groups (N divisible by 4)
#define SCAN_NB ((N4 + 1023) / 1024) // 13 scan blocks

// ---------------------------------------------------------------------------
// Scratch (device globals: no allocation allowed)
// ---------------------------------------------------------------------------
__device__ __half  g_fth[N_NODES * HD];      // 25.6 MB : projected features (half)
__device__ __align__(16) float g_el[N_NODES * H];
__device__ __align__(16) float g_er[N_NODES * H];
__device__ __align__(16) int   g_deg[N_NODES];
__device__ __align__(16) int   g_off[N_NODES + 4];
__device__ __align__(16) int   g_cur[N_NODES];
__device__ int    g_bsum[SCAN_NB];
__device__ int    g_boff[SCAN_NB];
__device__ int    g_csrc[E_EDGES];           // CSR: src node per slot
__device__ float4 g_eval[E_EDGES];           // CSR: 4-head logits per slot

__device__ __forceinline__ float lrelu(float x, float s) {
    return x >= 0.0f ? x : s * x;
}

// ---------------------------------------------------------------------------
// K0: zero degree histogram
// ---------------------------------------------------------------------------
__global__ void k_init() {
    int i = blockIdx.x * blockDim.x + threadIdx.x;
    int stride = gridDim.x * blockDim.x;
    for (int j = i; j < N_NODES; j += stride) g_deg[j] = 0;
}

// ---------------------------------------------------------------------------
// K1: degree histogram over dst (int4 vectorized; E divisible by 4)
// ---------------------------------------------------------------------------
__global__ __launch_bounds__(256) void k_hist(const int* __restrict__ dst) {
    int i = blockIdx.x * blockDim.x + threadIdx.x;
    if (i >= E_EDGES / 4) return;
    int4 d = ((const int4*)dst)[i];
    atomicAdd(&g_deg[d.x], 1);
    atomicAdd(&g_deg[d.y], 1);
    atomicAdd(&g_deg[d.z], 1);
    atomicAdd(&g_deg[d.w], 1);
}

// ---------------------------------------------------------------------------
// K2a: per-block int4 scan (13 blocks x 1024 threads x 4 elems)
// ---------------------------------------------------------------------------
__global__ __launch_bounds__(1024) void k_scan_a() {
    __shared__ int wsum[32];
    int tid  = threadIdx.x;
    int lane = tid & 31;
    int w    = tid >> 5;
    int i4   = blockIdx.x * 1024 + tid;

    int4 v = (i4 < N4) ? ((const int4*)g_deg)[i4] : make_int4(0, 0, 0, 0);
    int tot = v.x + v.y + v.z + v.w;
    int x = tot;
#pragma unroll
    for (int o = 1; o < 32; o <<= 1) {
        int y = __shfl_up_sync(0xffffffffu, x, o);
        if (lane >= o) x += y;
    }
    if (lane == 31) wsum[w] = x;
    __syncthreads();
    if (w == 0) {
        int y = wsum[lane];
#pragma unroll
        for (int o = 1; o < 32; o <<= 1) {
            int z = __shfl_up_sync(0xffffffffu, y, o);
            if (lane >= o) y += z;
        }
        wsum[lane] = y;
    }
    __syncthreads();
    int excl = (w > 0 ? wsum[w - 1] : 0) + x - tot;
    if (i4 < N4)
        ((int4*)g_off)[i4] = make_int4(excl, excl + v.x, excl + v.x + v.y,
                                       excl + v.x + v.y + v.z);
    if (tid == 0) g_bsum[blockIdx.x] = wsum[31];
}

// ---------------------------------------------------------------------------
// K2b: scan the 13 block sums (single warp)
// ---------------------------------------------------------------------------
__global__ void k_scan_b() {
    int lane = threadIdx.x;
    int v = (lane < SCAN_NB) ? g_bsum[lane] : 0;
    int x = v;
#pragma unroll
    for (int o = 1; o < 32; o <<= 1) {
        int y = __shfl_up_sync(0xffffffffu, x, o);
        if (lane >= o) x += y;
    }
    if (lane < SCAN_NB) g_boff[lane] = x - v;
    if (lane == 0) g_off[N_NODES] = E_EDGES;
}

// ---------------------------------------------------------------------------
// K2c: apply block offsets, mirror into g_cur
// ---------------------------------------------------------------------------
__global__ __launch_bounds__(1024) void k_scan_c() {
    int i4 = blockIdx.x * 1024 + threadIdx.x;
    if (i4 >= N4) return;
    int off = g_boff[blockIdx.x];
    int4 v = ((const int4*)g_off)[i4];
    v.x += off; v.y += off; v.z += off; v.w += off;
    ((int4*)g_off)[i4] = v;
    ((int4*)g_cur)[i4] = v;
}

// ---------------------------------------------------------------------------
// K3: ft = feat @ fc_w^T  (M=50000, N=256, K=256)  fp16 MMA m16n8k16
//     Epilogue: write half features + el/er via 4-lane shuffle reduce.
// ---------------------------------------------------------------------------
#define GBM 128
#define GBN 128
#define GBK 32
#define KP  20   // half2 row stride: 20 uint32 -> conflict-free fragment LDS

__global__ __launch_bounds__(256) void k_gemm(const float* __restrict__ A,
                                              const float* __restrict__ W,
                                              const float* __restrict__ attn_l,
                                              const float* __restrict__ attn_r) {
    __shared__ uint32_t As2[GBM][KP];
    __shared__ uint32_t Bs2[GBN][KP];

    const int bm   = blockIdx.x * GBM;
    const int bn   = blockIdx.y * GBN;
    const int tid  = threadIdx.x;
    const int wid  = tid >> 5;
    const int lane = tid & 31;
    const int wm   = wid & 3;          // 0..3  -> 32 rows each
    const int wn   = wid >> 2;         // 0..1  -> 64 cols each
    const int g    = lane >> 2;        // group id 0..7
    const int t    = lane & 3;         // thread-in-group 0..3

    float c[2][8][4];
#pragma unroll
    for (int i = 0; i < 2; i++)
#pragma unroll
        for (int j = 0; j < 8; j++)
#pragma unroll
            for (int q = 0; q < 4; q++) c[i][j][q] = 0.0f;

    for (int k0 = 0; k0 < IN_F; k0 += GBK) {
#pragma unroll
        for (int l = 0; l < 4; l++) {
            int fidx = tid + l * 256;      // 0..1023 float4 slots
            int row  = fidx >> 3;          // 0..127
            int col4 = (fidx & 7) * 4;     // float col within tile
            int gr   = bm + row;
            float4 va = make_float4(0.f, 0.f, 0.f, 0.f);
            if (gr < N_NODES) va = *(const float4*)&A[(size_t)gr * IN_F + k0 + col4];
            __half2 a0 = __float22half2_rn(make_float2(va.x, va.y));
            __half2 a1 = __float22half2_rn(make_float2(va.z, va.w));
            uint2 pa = make_uint2(*(uint32_t*)&a0, *(uint32_t*)&a1);
            *(uint2*)&As2[row][col4 >> 1] = pa;

            float4 vb = *(const float4*)&W[(size_t)(bn + row) * IN_F + k0 + col4];
            __half2 b0 = __float22half2_rn(make_float2(vb.x, vb.y));
            __half2 b1 = __float22half2_rn(make_float2(vb.z, vb.w));
            uint2 pb = make_uint2(*(uint32_t*)&b0, *(uint32_t*)&b1);
            *(uint2*)&Bs2[row][col4 >> 1] = pb;
        }
        __syncthreads();

#pragma unroll
        for (int ks = 0; ks < 2; ks++) {      // two k16 steps per 32-k tile
            const int kb = ks * 8;            // half2 offset
            uint32_t a[2][4];
#pragma unroll
            for (int i = 0; i < 2; i++) {
                int r0 = wm * 32 + i * 16;
                a[i][0] = As2[r0 + g    ][kb + t    ];
                a[i][1] = As2[r0 + g + 8][kb + t    ];
                a[i][2] = As2[r0 + g    ][kb + t + 4];
                a[i][3] = As2[r0 + g + 8][kb + t + 4];
            }
            uint32_t b[8][2];
#pragma unroll
            for (int j = 0; j < 8; j++) {
                int n0 = wn * 64 + j * 8;
                b[j][0] = Bs2[n0 + g][kb + t    ];
                b[j][1] = Bs2[n0 + g][kb + t + 4];
            }
#pragma unroll
            for (int i = 0; i < 2; i++)
#pragma unroll
                for (int j = 0; j < 8; j++) {
                    asm volatile(
                        "mma.sync.aligned.m16n8k16.row.col.f32.f16.f16.f32 "
                        "{%0,%1,%2,%3},{%4,%5,%6,%7},{%8,%9},{%0,%1,%2,%3};"
                        : "+f"(c[i][j][0]), "+f"(c[i][j][1]),
                          "+f"(c[i][j][2]), "+f"(c[i][j][3])
                        : "r"(a[i][0]), "r"(a[i][1]), "r"(a[i][2]), "r"(a[i][3]),
                          "r"(b[j][0]), "r"(b[j][1]));
                }
        }
        __syncthreads();
    }

    // epilogue: each thread's 16 cols live in exactly one head block of 64
    const int h = (bn + wn * 64) >> 6;                // head index 0..3
    const float* al = attn_l + h * D;
    const float* ar = attn_r + h * D;

#pragma unroll
    for (int i = 0; i < 2; i++) {
        int r0 = bm + wm * 32 + i * 16;
        int ra = r0 + g, rb = r0 + g + 8;
        float ela = 0.f, era = 0.f, elb = 0.f, erb = 0.f;
#pragma unroll
        for (int j = 0; j < 8; j++) {
            int dcol = j * 8 + t * 2;                 // col within head (0..62)
            int col  = bn + wn * 64 + dcol;           // global col
            float a0 = __ldg(&al[dcol]), a1 = __ldg(&al[dcol + 1]);
            float b0 = __ldg(&ar[dcol]), b1 = __ldg(&ar[dcol + 1]);
            ela = fmaf(c[i][j][0], a0, fmaf(c[i][j][1], a1, ela));
            era = fmaf(c[i][j][0], b0, fmaf(c[i][j][1], b1, era));
            elb = fmaf(c[i][j][2], a0, fmaf(c[i][j][3], a1, elb));
            erb = fmaf(c[i][j][2], b0, fmaf(c[i][j][3], b1, erb));
            if (ra < N_NODES)
                *(__half2*)&g_fth[(size_t)ra * HD + col] =
                    __float22half2_rn(make_float2(c[i][j][0], c[i][j][1]));
            if (rb < N_NODES)
                *(__half2*)&g_fth[(size_t)rb * HD + col] =
                    __float22half2_rn(make_float2(c[i][j][2], c[i][j][3]));
        }
        // reduce across the 4 consecutive lanes (t = 0..3) owning this row+head
#pragma unroll
        for (int o = 2; o > 0; o >>= 1) {
            ela += __shfl_down_sync(0xffffffffu, ela, o);
            era += __shfl_down_sync(0xffffffffu, era, o);
            elb += __shfl_down_sync(0xffffffffu, elb, o);
            erb += __shfl_down_sync(0xffffffffu, erb, o);
        }
        if (t == 0) {
            if (ra < N_NODES) { g_el[ra * H + h] = ela; g_er[ra * H + h] = era; }
            if (rb < N_NODES) { g_el[rb * H + h] = elb; g_er[rb * H + h] = erb; }
        }
    }
}

// ---------------------------------------------------------------------------
// K4: per-edge logits + scatter into CSR slots
// ---------------------------------------------------------------------------
__global__ __launch_bounds__(256) void k_build(const int* __restrict__ src,
                                               const int* __restrict__ dst,
                                               const int* __restrict__ etype,
                                               const float* __restrict__ edge_weight) {
    int e = blockIdx.x * blockDim.x + threadIdx.x;
    if (e >= E_EDGES) return;
    int s = src[e], d = dst[e], t = etype[e] - 1;
    float4 elv = *(const float4*)&g_el[s * H];
    float4 erv = *(const float4*)&g_er[d * H];
    float el4[4] = {elv.x, elv.y, elv.z, elv.w};
    float er4[4] = {erv.x, erv.y, erv.z, erv.w};
    float ve[4];
#pragma unroll
    for (int h = 0; h < H; h++) {
        float w = lrelu(__ldg(&edge_weight[t * H + h]) * ALPHA, SLOPE_EW);
        ve[h] = lrelu((el4[h] + er4[h]) * w, SLOPE_ATTN);
    }
    int pos = atomicAdd(&g_cur[d], 1);
    g_csrc[pos] = s;
    g_eval[pos] = make_float4(ve[0], ve[1], ve[2], ve[3]);
}

// ---------------------------------------------------------------------------
// K5: fused edge-softmax + weighted aggregate. One warp per dst node.
//     Lane owns 8 CONTIGUOUS output elements -> one uint4 (8 halves) load
//     per edge; head = lane>>3 is lane-constant.
// ---------------------------------------------------------------------------
__global__ __launch_bounds__(256) void k_fused(float* __restrict__ out) {
    __shared__ float s_cf[8][32 * 4];     // [warp][edge*4 + head]
    __shared__ int   s_src[8][32];

    int w    = threadIdx.x >> 5;
    int lane = threadIdx.x & 31;
    int n    = blockIdx.x * 8 + w;
    if (n >= N_NODES) return;

    int beg = g_off[n];
    int cnt = g_off[n + 1] - beg;

    float* orow = &out[(size_t)n * HD + lane * 8];
    if (cnt == 0) {
        float4 z = make_float4(0.f, 0.f, 0.f, 0.f);
        *(float4*)&orow[0] = z;
        *(float4*)&orow[4] = z;
        return;
    }

    // pass 1: per-head max
    float4 mx = make_float4(-INFINITY, -INFINITY, -INFINITY, -INFINITY);
    for (int i = lane; i < cnt; i += 32) {
        float4 v = g_eval[beg + i];
        mx.x = fmaxf(mx.x, v.x); mx.y = fmaxf(mx.y, v.y);
        mx.z = fmaxf(mx.z, v.z); mx.w = fmaxf(mx.w, v.w);
    }
#pragma unroll
    for (int o = 16; o > 0; o >>= 1) {
        mx.x = fmaxf(mx.x, __shfl_xor_sync(0xffffffffu, mx.x, o));
        mx.y = fmaxf(mx.y, __shfl_xor_sync(0xffffffffu, mx.y, o));
        mx.z = fmaxf(mx.z, __shfl_xor_sync(0xffffffffu, mx.z, o));
        mx.w = fmaxf(mx.w, __shfl_xor_sync(0xffffffffu, mx.w, o));
    }

    // pass 2: exp coefficients + denominator + register-accumulated aggregate
    const int hsel = lane >> 3;
    const uint4* __restrict__ fth = (const uint4*)g_fth;   // 32 uint4 per node

    float acc[8];
#pragma unroll
    for (int q = 0; q < 8; q++) acc[q] = 0.0f;
    float4 den = make_float4(0.f, 0.f, 0.f, 0.f);

    for (int base = 0; base < cnt; base += 32) {
        int i = base + lane;
        int m = min(32, cnt - base);
        if (i < cnt) {
            float4 v = g_eval[beg + i];
            float4 cf;
            cf.x = __expf(v.x - mx.x);
            cf.y = __expf(v.y - mx.y);
            cf.z = __expf(v.z - mx.z);
            cf.w = __expf(v.w - mx.w);
            den.x += cf.x; den.y += cf.y; den.z += cf.z; den.w += cf.w;
            s_cf[w][lane * 4 + 0] = cf.x;
            s_cf[w][lane * 4 + 1] = cf.y;
            s_cf[w][lane * 4 + 2] = cf.z;
            s_cf[w][lane * 4 + 3] = cf.w;
            s_src[w][lane] = g_csrc[beg + i];
        }
        __syncwarp();
#pragma unroll 4
        for (int j = 0; j < m; j++) {
            int   sidx = s_src[w][j];
            float cf   = s_cf[w][j * 4 + hsel];
            uint4 hv   = __ldg(&fth[(size_t)sidx * 32 + lane]);
            const __half2* hp = (const __half2*)&hv;
#pragma unroll
            for (int p = 0; p < 4; p++) {
                float2 f2 = __half22float2(hp[p]);
                acc[2 * p + 0] = fmaf(cf, f2.x, acc[2 * p + 0]);
                acc[2 * p + 1] = fmaf(cf, f2.y, acc[2 * p + 1]);
            }
        }
        __syncwarp();
    }

    // reduce denominator across warp, normalize, write row once
#pragma unroll
    for (int o = 16; o > 0; o >>= 1) {
        den.x += __shfl_xor_sync(0xffffffffu, den.x, o);
        den.y += __shfl_xor_sync(0xffffffffu, den.y, o);
        den.z += __shfl_xor_sync(0xffffffffu, den.z, o);
        den.w += __shfl_xor_sync(0xffffffffu, den.w, o);
    }
    float dh[4] = {den.x, den.y, den.z, den.w};
    float rd = 1.0f / dh[hsel];
    float4 o0 = make_float4(acc[0] * rd, acc[1] * rd, acc[2] * rd, acc[3] * rd);
    float4 o1 = make_float4(acc[4] * rd, acc[5] * rd, acc[6] * rd, acc[7] * rd);
    *(float4*)&orow[0] = o0;
    *(float4*)&orow[4] = o1;
}

// ---------------------------------------------------------------------------
// launch
// ---------------------------------------------------------------------------
extern "C" void kernel_launch(void* const* d_in, const int* in_sizes, int n_in,
                              void* d_out, int out_size) {
    const float* feat        = (const float*)d_in[0];
    const int*   src         = (const int*)  d_in[1];
    const int*   dst         = (const int*)  d_in[2];
    const int*   edge_feats  = (const int*)  d_in[3];
    const float* fc_w        = (const float*)d_in[4];
    const float* attn_l      = (const float*)d_in[5];
    const float* attn_r      = (const float*)d_in[6];
    const float* edge_weight = (const float*)d_in[7];
    float* out = (float*)d_out;

    k_init<<<256, 256>>>();
    k_hist<<<(E_EDGES / 4 + 255) / 256, 256>>>(dst);
    k_scan_a<<<SCAN_NB, 1024>>>();
    k_scan_b<<<1, 32>>>();
    k_scan_c<<<SCAN_NB, 1024>>>();

    dim3 gemm_grid((N_NODES + GBM - 1) / GBM, HD / GBN);   // (391, 2)
    k_gemm<<<gemm_grid, 256>>>(feat, fc_w, attn_l, attn_r);

    k_build<<<(E_EDGES + 255) / 256, 256>>>(src, dst, edge_feats, edge_weight);

    k_fused<<<(N_NODES + 7) / 8, 256>>>(out);
}

// round 9
// speedup vs baseline: 3.5419x; 1.0248x over previous
#include <cuda_runtime.h>
#include <cuda_fp16.h>
#include <math.h>
#include <stdint.h>

// ---------------------------------------------------------------------------
// Problem constants (fixed by the dataset)
// ---------------------------------------------------------------------------
#define N_NODES 50000
#define E_EDGES 800000
#define IN_F    256
#define H       4
#define D       64
#define HD      256     // H*D
#define ALPHA   100.0f
#define SLOPE_ATTN 0.2f
#define SLOPE_EW   0.01f

#define N4      (N_NODES / 4)        // 12500 int4 groups (N divisible by 4)
#define SCAN_NB ((N4 + 1023) / 1024) // 13 scan blocks

// ---------------------------------------------------------------------------
// Scratch (device globals: no allocation allowed).
// NOTE: g_deg relies on zero-initialization at module load; k_scan_a re-zeros
// it after reading, so it is zero again at the start of every call.
// ---------------------------------------------------------------------------
__device__ __half  g_fth[N_NODES * HD];      // 25.6 MB : projected features (half)
__device__ __align__(16) float g_el[N_NODES * H];
__device__ __align__(16) float g_er[N_NODES * H];
__device__ __align__(16) int   g_deg[N_NODES];
__device__ __align__(16) int   g_off[N_NODES + 4];
__device__ __align__(16) int   g_cur[N_NODES];
__device__ int    g_bsum[SCAN_NB];
__device__ int    g_csrc[E_EDGES];           // CSR: src node per slot
__device__ float4 g_eval[E_EDGES];           // CSR: 4-head logits per slot

__device__ __forceinline__ float lrelu(float x, float s) {
    return x >= 0.0f ? x : s * x;
}

// ---------------------------------------------------------------------------
// K1: degree histogram over dst (int4 vectorized; E divisible by 4)
// ---------------------------------------------------------------------------
__global__ __launch_bounds__(256) void k_hist(const int* __restrict__ dst) {
    int i = blockIdx.x * blockDim.x + threadIdx.x;
    if (i >= E_EDGES / 4) return;
    int4 d = ((const int4*)dst)[i];
    atomicAdd(&g_deg[d.x], 1);
    atomicAdd(&g_deg[d.y], 1);
    atomicAdd(&g_deg[d.z], 1);
    atomicAdd(&g_deg[d.w], 1);
}

// ---------------------------------------------------------------------------
// K2a: per-block int4 scan; also re-zeros g_deg for the next call
// ---------------------------------------------------------------------------
__global__ __launch_bounds__(1024) void k_scan_a() {
    __shared__ int wsum[32];
    int tid  = threadIdx.x;
    int lane = tid & 31;
    int w    = tid >> 5;
    int i4   = blockIdx.x * 1024 + tid;

    int4 v = make_int4(0, 0, 0, 0);
    if (i4 < N4) {
        v = ((const int4*)g_deg)[i4];
        ((int4*)g_deg)[i4] = make_int4(0, 0, 0, 0);   // restore invariant
    }
    int tot = v.x + v.y + v.z + v.w;
    int x = tot;
#pragma unroll
    for (int o = 1; o < 32; o <<= 1) {
        int y = __shfl_up_sync(0xffffffffu, x, o);
        if (lane >= o) x += y;
    }
    if (lane == 31) wsum[w] = x;
    __syncthreads();
    if (w == 0) {
        int y = wsum[lane];
#pragma unroll
        for (int o = 1; o < 32; o <<= 1) {
            int z = __shfl_up_sync(0xffffffffu, y, o);
            if (lane >= o) y += z;
        }
        wsum[lane] = y;
    }
    __syncthreads();
    int excl = (w > 0 ? wsum[w - 1] : 0) + x - tot;
    if (i4 < N4)
        ((int4*)g_off)[i4] = make_int4(excl, excl + v.x, excl + v.x + v.y,
                                       excl + v.x + v.y + v.z);
    if (tid == 0) g_bsum[blockIdx.x] = wsum[31];
}

// ---------------------------------------------------------------------------
// K2b: apply block offsets (each block scans the 13 block sums itself),
//      mirror into g_cur
// ---------------------------------------------------------------------------
__global__ __launch_bounds__(1024) void k_scan_c() {
    __shared__ int s_off;
    if (threadIdx.x < 32) {
        int lane = threadIdx.x;
        int v = (lane < SCAN_NB) ? g_bsum[lane] : 0;
        int x = v;
#pragma unroll
        for (int o = 1; o < 32; o <<= 1) {
            int y = __shfl_up_sync(0xffffffffu, x, o);
            if (lane >= o) x += y;
        }
        if (lane == (int)blockIdx.x) s_off = x - v;   // exclusive prefix
    }
    __syncthreads();
    int i4 = blockIdx.x * 1024 + threadIdx.x;
    if (blockIdx.x == 0 && threadIdx.x == 0) g_off[N_NODES] = E_EDGES;
    if (i4 >= N4) return;
    int off = s_off;
    int4 v = ((const int4*)g_off)[i4];
    v.x += off; v.y += off; v.z += off; v.w += off;
    ((int4*)g_off)[i4] = v;
    ((int4*)g_cur)[i4] = v;
}

// ---------------------------------------------------------------------------
// K3: ft = feat @ fc_w^T  (M=50000, N=256, K=256)  fp16 MMA m16n8k16
//     Register-pipelined global loads; epilogue writes half ft + el/er.
// ---------------------------------------------------------------------------
#define GBM 128
#define GBN 128
#define GBK 32
#define KP  20   // half2 row stride: 20 uint32 -> conflict-free fragment LDS

__global__ __launch_bounds__(256) void k_gemm(const float* __restrict__ A,
                                              const float* __restrict__ W,
                                              const float* __restrict__ attn_l,
                                              const float* __restrict__ attn_r) {
    __shared__ uint32_t As2[GBM][KP];
    __shared__ uint32_t Bs2[GBN][KP];

    const int bm   = blockIdx.x * GBM;
    const int bn   = blockIdx.y * GBN;
    const int tid  = threadIdx.x;
    const int wid  = tid >> 5;
    const int lane = tid & 31;
    const int wm   = wid & 3;          // 0..3  -> 32 rows each
    const int wn   = wid >> 2;         // 0..1  -> 64 cols each
    const int g    = lane >> 2;        // group id 0..7
    const int t    = lane & 3;         // thread-in-group 0..3

    // per-thread load coordinates (4 float4 per matrix per tile)
    int lrow[4], lcol[4];
#pragma unroll
    for (int l = 0; l < 4; l++) {
        int fidx = tid + l * 256;
        lrow[l] = fidx >> 3;
        lcol[l] = (fidx & 7) * 4;
    }

    float c[2][8][4];
#pragma unroll
    for (int i = 0; i < 2; i++)
#pragma unroll
        for (int j = 0; j < 8; j++)
#pragma unroll
            for (int q = 0; q < 4; q++) c[i][j][q] = 0.0f;

    float4 va[4], vb[4];
    // prologue: load k-tile 0
#pragma unroll
    for (int l = 0; l < 4; l++) {
        int gr = bm + lrow[l];
        va[l] = make_float4(0.f, 0.f, 0.f, 0.f);
        if (gr < N_NODES) va[l] = *(const float4*)&A[(size_t)gr * IN_F + lcol[l]];
        vb[l] = *(const float4*)&W[(size_t)(bn + lrow[l]) * IN_F + lcol[l]];
    }

    for (int k0 = 0; k0 < IN_F; k0 += GBK) {
        // convert + store current tile to smem
#pragma unroll
        for (int l = 0; l < 4; l++) {
            __half2 a0 = __float22half2_rn(make_float2(va[l].x, va[l].y));
            __half2 a1 = __float22half2_rn(make_float2(va[l].z, va[l].w));
            *(uint2*)&As2[lrow[l]][lcol[l] >> 1] =
                make_uint2(*(uint32_t*)&a0, *(uint32_t*)&a1);
            __half2 b0 = __float22half2_rn(make_float2(vb[l].x, vb[l].y));
            __half2 b1 = __float22half2_rn(make_float2(vb[l].z, vb[l].w));
            *(uint2*)&Bs2[lrow[l]][lcol[l] >> 1] =
                make_uint2(*(uint32_t*)&b0, *(uint32_t*)&b1);
        }
        __syncthreads();

        // prefetch next tile into registers (overlaps with mma below)
        int kn = k0 + GBK;
        if (kn < IN_F) {
#pragma unroll
            for (int l = 0; l < 4; l++) {
                int gr = bm + lrow[l];
                va[l] = make_float4(0.f, 0.f, 0.f, 0.f);
                if (gr < N_NODES)
                    va[l] = *(const float4*)&A[(size_t)gr * IN_F + kn + lcol[l]];
                vb[l] = *(const float4*)&W[(size_t)(bn + lrow[l]) * IN_F + kn + lcol[l]];
            }
        }

#pragma unroll
        for (int ks = 0; ks < 2; ks++) {      // two k16 steps per 32-k tile
            const int kb = ks * 8;            // half2 offset
            uint32_t a[2][4];
#pragma unroll
            for (int i = 0; i < 2; i++) {
                int r0 = wm * 32 + i * 16;
                a[i][0] = As2[r0 + g    ][kb + t    ];
                a[i][1] = As2[r0 + g + 8][kb + t    ];
                a[i][2] = As2[r0 + g    ][kb + t + 4];
                a[i][3] = As2[r0 + g + 8][kb + t + 4];
            }
            uint32_t b[8][2];
#pragma unroll
            for (int j = 0; j < 8; j++) {
                int n0 = wn * 64 + j * 8;
                b[j][0] = Bs2[n0 + g][kb + t    ];
                b[j][1] = Bs2[n0 + g][kb + t + 4];
            }
#pragma unroll
            for (int i = 0; i < 2; i++)
#pragma unroll
                for (int j = 0; j < 8; j++) {
                    asm volatile(
                        "mma.sync.aligned.m16n8k16.row.col.f32.f16.f16.f32 "
                        "{%0,%1,%2,%3},{%4,%5,%6,%7},{%8,%9},{%0,%1,%2,%3};"
                        : "+f"(c[i][j][0]), "+f"(c[i][j][1]),
                          "+f"(c[i][j][2]), "+f"(c[i][j][3])
                        : "r"(a[i][0]), "r"(a[i][1]), "r"(a[i][2]), "r"(a[i][3]),
                          "r"(b[j][0]), "r"(b[j][1]));
                }
        }
        __syncthreads();
    }

    // epilogue: each thread's 16 cols live in exactly one head block of 64
    const int h = (bn + wn * 64) >> 6;                // head index 0..3
    const float* al = attn_l + h * D;
    const float* ar = attn_r + h * D;

#pragma unroll
    for (int i = 0; i < 2; i++) {
        int r0 = bm + wm * 32 + i * 16;
        int ra = r0 + g, rb = r0 + g + 8;
        float ela = 0.f, era = 0.f, elb = 0.f, erb = 0.f;
#pragma unroll
        for (int j = 0; j < 8; j++) {
            int dcol = j * 8 + t * 2;                 // col within head (0..62)
            int col  = bn + wn * 64 + dcol;           // global col
            float a0 = __ldg(&al[dcol]), a1 = __ldg(&al[dcol + 1]);
            float b0 = __ldg(&ar[dcol]), b1 = __ldg(&ar[dcol + 1]);
            ela = fmaf(c[i][j][0], a0, fmaf(c[i][j][1], a1, ela));
            era = fmaf(c[i][j][0], b0, fmaf(c[i][j][1], b1, era));
            elb = fmaf(c[i][j][2], a0, fmaf(c[i][j][3], a1, elb));
            erb = fmaf(c[i][j][2], b0, fmaf(c[i][j][3], b1, erb));
            if (ra < N_NODES)
                *(__half2*)&g_fth[(size_t)ra * HD + col] =
                    __float22half2_rn(make_float2(c[i][j][0], c[i][j][1]));
            if (rb < N_NODES)
                *(__half2*)&g_fth[(size_t)rb * HD + col] =
                    __float22half2_rn(make_float2(c[i][j][2], c[i][j][3]));
        }
        // reduce across the 4 consecutive lanes (t = 0..3) owning this row+head
#pragma unroll
        for (int o = 2; o > 0; o >>= 1) {
            ela += __shfl_down_sync(0xffffffffu, ela, o);
            era += __shfl_down_sync(0xffffffffu, era, o);
            elb += __shfl_down_sync(0xffffffffu, elb, o);
            erb += __shfl_down_sync(0xffffffffu, erb, o);
        }
        if (t == 0) {
            if (ra < N_NODES) { g_el[ra * H + h] = ela; g_er[ra * H + h] = era; }
            if (rb < N_NODES) { g_el[rb * H + h] = elb; g_er[rb * H + h] = erb; }
        }
    }
}

// ---------------------------------------------------------------------------
// K4: per-edge logits + scatter into CSR slots
// ---------------------------------------------------------------------------
__global__ __launch_bounds__(256) void k_build(const int* __restrict__ src,
                                               const int* __restrict__ dst,
                                               const int* __restrict__ etype,
                                               const float* __restrict__ edge_weight) {
    int e = blockIdx.x * blockDim.x + threadIdx.x;
    if (e >= E_EDGES) return;
    int s = src[e], d = dst[e], t = etype[e] - 1;
    float4 elv = *(const float4*)&g_el[s * H];
    float4 erv = *(const float4*)&g_er[d * H];
    float el4[4] = {elv.x, elv.y, elv.z, elv.w};
    float er4[4] = {erv.x, erv.y, erv.z, erv.w};
    float ve[4];
#pragma unroll
    for (int h = 0; h < H; h++) {
        float w = lrelu(__ldg(&edge_weight[t * H + h]) * ALPHA, SLOPE_EW);
        ve[h] = lrelu((el4[h] + er4[h]) * w, SLOPE_ATTN);
    }
    int pos = atomicAdd(&g_cur[d], 1);
    g_csrc[pos] = s;
    g_eval[pos] = make_float4(ve[0], ve[1], ve[2], ve[3]);
}

// ---------------------------------------------------------------------------
// K5: fused edge-softmax + weighted aggregate. One warp per dst node.
// ---------------------------------------------------------------------------
__global__ __launch_bounds__(256) void k_fused(float* __restrict__ out) {
    __shared__ float s_cf[8][32 * 4];     // [warp][edge*4 + head]
    __shared__ int   s_src[8][32];

    int w    = threadIdx.x >> 5;
    int lane = threadIdx.x & 31;
    int n    = blockIdx.x * 8 + w;
    if (n >= N_NODES) return;

    int beg = g_off[n];
    int cnt = g_off[n + 1] - beg;

    float* orow = &out[(size_t)n * HD + lane * 8];
    if (cnt == 0) {
        float4 z = make_float4(0.f, 0.f, 0.f, 0.f);
        *(float4*)&orow[0] = z;
        *(float4*)&orow[4] = z;
        return;
    }

    // pass 1: per-head max
    float4 mx = make_float4(-INFINITY, -INFINITY, -INFINITY, -INFINITY);
    for (int i = lane; i < cnt; i += 32) {
        float4 v = g_eval[beg + i];
        mx.x = fmaxf(mx.x, v.x); mx.y = fmaxf(mx.y, v.y);
        mx.z = fmaxf(mx.z, v.z); mx.w = fmaxf(mx.w, v.w);
    }
#pragma unroll
    for (int o = 16; o > 0; o >>= 1) {
        mx.x = fmaxf(mx.x, __shfl_xor_sync(0xffffffffu, mx.x, o));
        mx.y = fmaxf(mx.y, __shfl_xor_sync(0xffffffffu, mx.y, o));
        mx.z = fmaxf(mx.z, __shfl_xor_sync(0xffffffffu, mx.z, o));
        mx.w = fmaxf(mx.w, __shfl_xor_sync(0xffffffffu, mx.w, o));
    }

    // pass 2: exp coefficients + denominator + register-accumulated aggregate
    const int hsel = lane >> 3;
    const uint4* __restrict__ fth = (const uint4*)g_fth;   // 32 uint4 per node

    float acc[8];
#pragma unroll
    for (int q = 0; q < 8; q++) acc[q] = 0.0f;
    float4 den = make_float4(0.f, 0.f, 0.f, 0.f);

    for (int base = 0; base < cnt; base += 32) {
        int i = base + lane;
        int m = min(32, cnt - base);
        if (i < cnt) {
            float4 v = g_eval[beg + i];
            float4 cf;
            cf.x = __expf(v.x - mx.x);
            cf.y = __expf(v.y - mx.y);
            cf.z = __expf(v.z - mx.z);
            cf.w = __expf(v.w - mx.w);
            den.x += cf.x; den.y += cf.y; den.z += cf.z; den.w += cf.w;
            s_cf[w][lane * 4 + 0] = cf.x;
            s_cf[w][lane * 4 + 1] = cf.y;
            s_cf[w][lane * 4 + 2] = cf.z;
            s_cf[w][lane * 4 + 3] = cf.w;
            s_src[w][lane] = g_csrc[beg + i];
        }
        __syncwarp();
#pragma unroll 4
        for (int j = 0; j < m; j++) {
            int   sidx = s_src[w][j];
            float cf   = s_cf[w][j * 4 + hsel];
            uint4 hv   = __ldg(&fth[(size_t)sidx * 32 + lane]);
            const __half2* hp = (const __half2*)&hv;
#pragma unroll
            for (int p = 0; p < 4; p++) {
                float2 f2 = __half22float2(hp[p]);
                acc[2 * p + 0] = fmaf(cf, f2.x, acc[2 * p + 0]);
                acc[2 * p + 1] = fmaf(cf, f2.y, acc[2 * p + 1]);
            }
        }
        __syncwarp();
    }

    // reduce denominator across warp, normalize, write row once
#pragma unroll
    for (int o = 16; o > 0; o >>= 1) {
        den.x += __shfl_xor_sync(0xffffffffu, den.x, o);
        den.y += __shfl_xor_sync(0xffffffffu, den.y, o);
        den.z += __shfl_xor_sync(0xffffffffu, den.z, o);
        den.w += __shfl_xor_sync(0xffffffffu, den.w, o);
    }
    float dh[4] = {den.x, den.y, den.z, den.w};
    float rd = 1.0f / dh[hsel];
    float4 o0 = make_float4(acc[0] * rd, acc[1] * rd, acc[2] * rd, acc[3] * rd);
    float4 o1 = make_float4(acc[4] * rd, acc[5] * rd, acc[6] * rd, acc[7] * rd);
    *(float4*)&orow[0] = o0;
    *(float4*)&orow[4] = o1;
}

// ---------------------------------------------------------------------------
// launch: fork CSR-build chain onto a side stream, overlap with GEMM
// ---------------------------------------------------------------------------
extern "C" void kernel_launch(void* const* d_in, const int* in_sizes, int n_in,
                              void* d_out, int out_size) {
    const float* feat        = (const float*)d_in[0];
    const int*   src         = (const int*)  d_in[1];
    const int*   dst         = (const int*)  d_in[2];
    const int*   edge_feats  = (const int*)  d_in[3];
    const float* fc_w        = (const float*)d_in[4];
    const float* attn_l      = (const float*)d_in[5];
    const float* attn_r      = (const float*)d_in[6];
    const float* edge_weight = (const float*)d_in[7];
    float* out = (float*)d_out;

    static cudaStream_t s_side = nullptr;
    static cudaEvent_t  ev_fork = nullptr, ev_join = nullptr;
    if (s_side == nullptr) {
        cudaStreamCreateWithFlags(&s_side, cudaStreamNonBlocking);
        cudaEventCreateWithFlags(&ev_fork, cudaEventDisableTiming);
        cudaEventCreateWithFlags(&ev_join, cudaEventDisableTiming);
    }

    // fork: CSR chain (depends only on dst) on side stream
    cudaEventRecord(ev_fork, 0);
    cudaStreamWaitEvent(s_side, ev_fork, 0);
    k_hist  <<<(E_EDGES / 4 + 255) / 256, 256, 0, s_side>>>(dst);
    k_scan_a<<<SCAN_NB, 1024, 0, s_side>>>();
    k_scan_c<<<SCAN_NB, 1024, 0, s_side>>>();
    cudaEventRecord(ev_join, s_side);

    // main stream: GEMM (independent of CSR chain)
    dim3 gemm_grid((N_NODES + GBM - 1) / GBM, HD / GBN);   // (391, 2)
    k_gemm<<<gemm_grid, 256>>>(feat, fc_w, attn_l, attn_r);

    // join, then dependent kernels
    cudaStreamWaitEvent(0, ev_join, 0);
    k_build<<<(E_EDGES + 255) / 256, 256>>>(src, dst, edge_feats, edge_weight);
    k_fused<<<(N_NODES + 7) / 8, 256>>>(out);
}

// round 10
// speedup vs baseline: 3.6649x; 1.0347x over previous
#include <cuda_runtime.h>
#include <cuda_fp16.h>
#include <math.h>
#include <stdint.h>

// ---------------------------------------------------------------------------
// Problem constants (fixed by the dataset)
// ---------------------------------------------------------------------------
#define N_NODES 50000
#define E_EDGES 800000
#define IN_F    256
#define H       4
#define D       64
#define HD      256     // H*D
#define ALPHA   100.0f
#define SLOPE_ATTN 0.2f
#define SLOPE_EW   0.01f

#define N4      (N_NODES / 4)        // 12500 int4 groups (N divisible by 4)
#define SCAN_NB ((N4 + 1023) / 1024) // 13 scan blocks

// ---------------------------------------------------------------------------
// Scratch (device globals: no allocation allowed).
// g_deg is zero at module load; k_scan_a re-zeros it after reading, so the
// all-zero invariant holds at the start of every call/replay.
// ---------------------------------------------------------------------------
__device__ __half  g_fth[N_NODES * HD];      // 25.6 MB : projected features (half)
__device__ __align__(16) float g_el[N_NODES * H];
__device__ __align__(16) float g_er[N_NODES * H];
__device__ __align__(16) int   g_deg[N_NODES];
__device__ __align__(16) int   g_off[N_NODES + 4];
__device__ __align__(16) int   g_cur[N_NODES];
__device__ int    g_bsum[SCAN_NB];
__device__ int    g_csrc[E_EDGES];           // CSR: src node per slot
__device__ float4 g_eval[E_EDGES];           // CSR: 4-head logits per slot

__device__ __forceinline__ float lrelu(float x, float s) {
    return x >= 0.0f ? x : s * x;
}
__device__ __forceinline__ uint32_t smem_u32(const void* p) {
    return (uint32_t)__cvta_generic_to_shared(p);
}
__device__ __forceinline__ void ldmatrix_x4(uint32_t& r0, uint32_t& r1,
                                            uint32_t& r2, uint32_t& r3,
                                            uint32_t addr) {
    asm volatile("ldmatrix.sync.aligned.m8n8.x4.shared.b16 {%0,%1,%2,%3}, [%4];"
                 : "=r"(r0), "=r"(r1), "=r"(r2), "=r"(r3) : "r"(addr));
}

// ---------------------------------------------------------------------------
// K1: degree histogram over dst (int4 vectorized; E divisible by 4)
// ---------------------------------------------------------------------------
__global__ __launch_bounds__(256) void k_hist(const int* __restrict__ dst) {
    int i = blockIdx.x * blockDim.x + threadIdx.x;
    if (i >= E_EDGES / 4) return;
    int4 d = ((const int4*)dst)[i];
    atomicAdd(&g_deg[d.x], 1);
    atomicAdd(&g_deg[d.y], 1);
    atomicAdd(&g_deg[d.z], 1);
    atomicAdd(&g_deg[d.w], 1);
}

// ---------------------------------------------------------------------------
// K2a: per-block int4 scan; also re-zeros g_deg for the next call
// ---------------------------------------------------------------------------
__global__ __launch_bounds__(1024) void k_scan_a() {
    __shared__ int wsum[32];
    int tid  = threadIdx.x;
    int lane = tid & 31;
    int w    = tid >> 5;
    int i4   = blockIdx.x * 1024 + tid;

    int4 v = make_int4(0, 0, 0, 0);
    if (i4 < N4) {
        v = ((const int4*)g_deg)[i4];
        ((int4*)g_deg)[i4] = make_int4(0, 0, 0, 0);   // restore invariant
    }
    int tot = v.x + v.y + v.z + v.w;
    int x = tot;
#pragma unroll
    for (int o = 1; o < 32; o <<= 1) {
        int y = __shfl_up_sync(0xffffffffu, x, o);
        if (lane >= o) x += y;
    }
    if (lane == 31) wsum[w] = x;
    __syncthreads();
    if (w == 0) {
        int y = wsum[lane];
#pragma unroll
        for (int o = 1; o < 32; o <<= 1) {
            int z = __shfl_up_sync(0xffffffffu, y, o);
            if (lane >= o) y += z;
        }
        wsum[lane] = y;
    }
    __syncthreads();
    int excl = (w > 0 ? wsum[w - 1] : 0) + x - tot;
    if (i4 < N4)
        ((int4*)g_off)[i4] = make_int4(excl, excl + v.x, excl + v.x + v.y,
                                       excl + v.x + v.y + v.z);
    if (tid == 0) g_bsum[blockIdx.x] = wsum[31];
}

// ---------------------------------------------------------------------------
// K2b: apply block offsets (each block scans the 13 block sums itself),
//      mirror into g_cur
// ---------------------------------------------------------------------------
__global__ __launch_bounds__(1024) void k_scan_c() {
    __shared__ int s_off;
    if (threadIdx.x < 32) {
        int lane = threadIdx.x;
        int v = (lane < SCAN_NB) ? g_bsum[lane] : 0;
        int x = v;
#pragma unroll
        for (int o = 1; o < 32; o <<= 1) {
            int y = __shfl_up_sync(0xffffffffu, x, o);
            if (lane >= o) x += y;
        }
        if (lane == (int)blockIdx.x) s_off = x - v;   // exclusive prefix
    }
    __syncthreads();
    int i4 = blockIdx.x * 1024 + threadIdx.x;
    if (blockIdx.x == 0 && threadIdx.x == 0) g_off[N_NODES] = E_EDGES;
    if (i4 >= N4) return;
    int off = s_off;
    int4 v = ((const int4*)g_off)[i4];
    v.x += off; v.y += off; v.z += off; v.w += off;
    ((int4*)g_off)[i4] = v;
    ((int4*)g_cur)[i4] = v;
}

// ---------------------------------------------------------------------------
// K3: ft = feat @ fc_w^T  (M=50000, N=256, K=256)  fp16 MMA m16n8k16
//     ldmatrix fragment loads + 2 CTAs/SM; epilogue writes half ft + el/er.
// ---------------------------------------------------------------------------
#define GBM 128
#define GBN 128
#define GBK 32
#define KP  20   // half2 row stride: 20 uint32 -> conflict-free LDS/LDSM

__global__ __launch_bounds__(256, 2) void k_gemm(const float* __restrict__ A,
                                                 const float* __restrict__ W,
                                                 const float* __restrict__ attn_l,
                                                 const float* __restrict__ attn_r) {
    __shared__ uint32_t As2[GBM][KP];
    __shared__ uint32_t Bs2[GBN][KP];

    const int bm   = blockIdx.x * GBM;
    const int bn   = blockIdx.y * GBN;
    const int tid  = threadIdx.x;
    const int wid  = tid >> 5;
    const int lane = tid & 31;
    const int wm   = wid & 3;          // 0..3  -> 32 rows each
    const int wn   = wid >> 2;         // 0..1  -> 64 cols each
    const int g    = lane >> 2;        // group id 0..7
    const int t    = lane & 3;         // thread-in-group 0..3

    // ldmatrix base addresses (k-offset added in loop)
    uint32_t a_base[2], b_base[4];
    {
        int arow = lane & 15;
        int acol = (lane >> 4) * 4;                 // uint32 offset within row
#pragma unroll
        for (int i = 0; i < 2; i++)
            a_base[i] = smem_u32(&As2[wm * 32 + i * 16 + arow][acol]);
        int brow = ((lane >> 4) << 3) + (lane & 7);
        int bcol = ((lane >> 3) & 1) * 4;
#pragma unroll
        for (int jp = 0; jp < 4; jp++)
            b_base[jp] = smem_u32(&Bs2[wn * 64 + jp * 16 + brow][bcol]);
    }

    float c[2][8][4];
#pragma unroll
    for (int i = 0; i < 2; i++)
#pragma unroll
        for (int j = 0; j < 8; j++)
#pragma unroll
            for (int q = 0; q < 4; q++) c[i][j][q] = 0.0f;

    for (int k0 = 0; k0 < IN_F; k0 += GBK) {
        // load + convert + store current k-tile
#pragma unroll
        for (int l = 0; l < 4; l++) {
            int fidx = tid + l * 256;      // 0..1023 float4 slots
            int row  = fidx >> 3;          // 0..127
            int col4 = (fidx & 7) * 4;     // float col within tile
            int gr   = bm + row;
            float4 va = make_float4(0.f, 0.f, 0.f, 0.f);
            if (gr < N_NODES) va = *(const float4*)&A[(size_t)gr * IN_F + k0 + col4];
            __half2 a0 = __float22half2_rn(make_float2(va.x, va.y));
            __half2 a1 = __float22half2_rn(make_float2(va.z, va.w));
            *(uint2*)&As2[row][col4 >> 1] =
                make_uint2(*(uint32_t*)&a0, *(uint32_t*)&a1);

            float4 vb = *(const float4*)&W[(size_t)(bn + row) * IN_F + k0 + col4];
            __half2 b0 = __float22half2_rn(make_float2(vb.x, vb.y));
            __half2 b1 = __float22half2_rn(make_float2(vb.z, vb.w));
            *(uint2*)&Bs2[row][col4 >> 1] =
                make_uint2(*(uint32_t*)&b0, *(uint32_t*)&b1);
        }
        __syncthreads();

#pragma unroll
        for (int ks = 0; ks < 2; ks++) {      // two k16 steps per 32-k tile
            const uint32_t koff = ks * 32;    // byte offset (8 uint32)
            uint32_t a[2][4];
#pragma unroll
            for (int i = 0; i < 2; i++)
                ldmatrix_x4(a[i][0], a[i][1], a[i][2], a[i][3], a_base[i] + koff);
            uint32_t b[8][2];
#pragma unroll
            for (int jp = 0; jp < 4; jp++)
                ldmatrix_x4(b[jp * 2][0], b[jp * 2][1],
                            b[jp * 2 + 1][0], b[jp * 2 + 1][1],
                            b_base[jp] + koff);
#pragma unroll
            for (int i = 0; i < 2; i++)
#pragma unroll
                for (int j = 0; j < 8; j++) {
                    asm volatile(
                        "mma.sync.aligned.m16n8k16.row.col.f32.f16.f16.f32 "
                        "{%0,%1,%2,%3},{%4,%5,%6,%7},{%8,%9},{%0,%1,%2,%3};"
                        : "+f"(c[i][j][0]), "+f"(c[i][j][1]),
                          "+f"(c[i][j][2]), "+f"(c[i][j][3])
                        : "r"(a[i][0]), "r"(a[i][1]), "r"(a[i][2]), "r"(a[i][3]),
                          "r"(b[j][0]), "r"(b[j][1]));
                }
        }
        __syncthreads();
    }

    // epilogue: each thread's 16 cols live in exactly one head block of 64
    const int h = (bn + wn * 64) >> 6;                // head index 0..3
    const float* al = attn_l + h * D;
    const float* ar = attn_r + h * D;

#pragma unroll
    for (int i = 0; i < 2; i++) {
        int r0 = bm + wm * 32 + i * 16;
        int ra = r0 + g, rb = r0 + g + 8;
        float ela = 0.f, era = 0.f, elb = 0.f, erb = 0.f;
#pragma unroll
        for (int j = 0; j < 8; j++) {
            int dcol = j * 8 + t * 2;                 // col within head (0..62)
            int col  = bn + wn * 64 + dcol;           // global col
            float a0 = __ldg(&al[dcol]), a1 = __ldg(&al[dcol + 1]);
            float b0 = __ldg(&ar[dcol]), b1 = __ldg(&ar[dcol + 1]);
            ela = fmaf(c[i][j][0], a0, fmaf(c[i][j][1], a1, ela));
            era = fmaf(c[i][j][0], b0, fmaf(c[i][j][1], b1, era));
            elb = fmaf(c[i][j][2], a0, fmaf(c[i][j][3], a1, elb));
            erb = fmaf(c[i][j][2], b0, fmaf(c[i][j][3], b1, erb));
            if (ra < N_NODES)
                *(__half2*)&g_fth[(size_t)ra * HD + col] =
                    __float22half2_rn(make_float2(c[i][j][0], c[i][j][1]));
            if (rb < N_NODES)
                *(__half2*)&g_fth[(size_t)rb * HD + col] =
                    __float22half2_rn(make_float2(c[i][j][2], c[i][j][3]));
        }
        // reduce across the 4 consecutive lanes (t = 0..3) owning this row+head
#pragma unroll
        for (int o = 2; o > 0; o >>= 1) {
            ela += __shfl_down_sync(0xffffffffu, ela, o);
            era += __shfl_down_sync(0xffffffffu, era, o);
            elb += __shfl_down_sync(0xffffffffu, elb, o);
            erb += __shfl_down_sync(0xffffffffu, erb, o);
        }
        if (t == 0) {
            if (ra < N_NODES) { g_el[ra * H + h] = ela; g_er[ra * H + h] = era; }
            if (rb < N_NODES) { g_el[rb * H + h] = elb; g_er[rb * H + h] = erb; }
        }
    }
}

// ---------------------------------------------------------------------------
// K4: per-edge logits + scatter into CSR slots
// ---------------------------------------------------------------------------
__global__ __launch_bounds__(256) void k_build(const int* __restrict__ src,
                                               const int* __restrict__ dst,
                                               const int* __restrict__ etype,
                                               const float* __restrict__ edge_weight) {
    int e = blockIdx.x * blockDim.x + threadIdx.x;
    if (e >= E_EDGES) return;
    int s = src[e], d = dst[e], t = etype[e] - 1;
    float4 elv = *(const float4*)&g_el[s * H];
    float4 erv = *(const float4*)&g_er[d * H];
    float el4[4] = {elv.x, elv.y, elv.z, elv.w};
    float er4[4] = {erv.x, erv.y, erv.z, erv.w};
    float ve[4];
#pragma unroll
    for (int h = 0; h < H; h++) {
        float w = lrelu(__ldg(&edge_weight[t * H + h]) * ALPHA, SLOPE_EW);
        ve[h] = lrelu((el4[h] + er4[h]) * w, SLOPE_ATTN);
    }
    int pos = atomicAdd(&g_cur[d], 1);
    g_csrc[pos] = s;
    g_eval[pos] = make_float4(ve[0], ve[1], ve[2], ve[3]);
}

// ---------------------------------------------------------------------------
// K5: fused edge-softmax + weighted aggregate. One warp per dst node.
// ---------------------------------------------------------------------------
__global__ __launch_bounds__(256) void k_fused(float* __restrict__ out) {
    __shared__ float s_cf[8][32 * 4];     // [warp][edge*4 + head]
    __shared__ int   s_src[8][32];

    int w    = threadIdx.x >> 5;
    int lane = threadIdx.x & 31;
    int n    = blockIdx.x * 8 + w;
    if (n >= N_NODES) return;

    int beg = g_off[n];
    int cnt = g_off[n + 1] - beg;

    float* orow = &out[(size_t)n * HD + lane * 8];
    if (cnt == 0) {
        float4 z = make_float4(0.f, 0.f, 0.f, 0.f);
        *(float4*)&orow[0] = z;
        *(float4*)&orow[4] = z;
        return;
    }

    // pass 1: per-head max
    float4 mx = make_float4(-INFINITY, -INFINITY, -INFINITY, -INFINITY);
    for (int i = lane; i < cnt; i += 32) {
        float4 v = g_eval[beg + i];
        mx.x = fmaxf(mx.x, v.x); mx.y = fmaxf(mx.y, v.y);
        mx.z = fmaxf(mx.z, v.z); mx.w = fmaxf(mx.w, v.w);
    }
#pragma unroll
    for (int o = 16; o > 0; o >>= 1) {
        mx.x = fmaxf(mx.x, __shfl_xor_sync(0xffffffffu, mx.x, o));
        mx.y = fmaxf(mx.y, __shfl_xor_sync(0xffffffffu, mx.y, o));
        mx.z = fmaxf(mx.z, __shfl_xor_sync(0xffffffffu, mx.z, o));
        mx.w = fmaxf(mx.w, __shfl_xor_sync(0xffffffffu, mx.w, o));
    }

    // pass 2: exp coefficients + denominator + register-accumulated aggregate
    const int hsel = lane >> 3;
    const uint4* __restrict__ fth = (const uint4*)g_fth;   // 32 uint4 per node

    float acc[8];
#pragma unroll
    for (int q = 0; q < 8; q++) acc[q] = 0.0f;
    float4 den = make_float4(0.f, 0.f, 0.f, 0.f);

    for (int base = 0; base < cnt; base += 32) {
        int i = base + lane;
        int m = min(32, cnt - base);
        if (i < cnt) {
            float4 v = g_eval[beg + i];
            float4 cf;
            cf.x = __expf(v.x - mx.x);
            cf.y = __expf(v.y - mx.y);
            cf.z = __expf(v.z - mx.z);
            cf.w = __expf(v.w - mx.w);
            den.x += cf.x; den.y += cf.y; den.z += cf.z; den.w += cf.w;
            s_cf[w][lane * 4 + 0] = cf.x;
            s_cf[w][lane * 4 + 1] = cf.y;
            s_cf[w][lane * 4 + 2] = cf.z;
            s_cf[w][lane * 4 + 3] = cf.w;
            s_src[w][lane] = g_csrc[beg + i];
        }
        __syncwarp();
#pragma unroll 4
        for (int j = 0; j < m; j++) {
            int   sidx = s_src[w][j];
            float cf   = s_cf[w][j * 4 + hsel];
            uint4 hv   = __ldg(&fth[(size_t)sidx * 32 + lane]);
            const __half2* hp = (const __half2*)&hv;
#pragma unroll
            for (int p = 0; p < 4; p++) {
                float2 f2 = __half22float2(hp[p]);
                acc[2 * p + 0] = fmaf(cf, f2.x, acc[2 * p + 0]);
                acc[2 * p + 1] = fmaf(cf, f2.y, acc[2 * p + 1]);
            }
        }
        __syncwarp();
    }

    // reduce denominator across warp, normalize, write row once
#pragma unroll
    for (int o = 16; o > 0; o >>= 1) {
        den.x += __shfl_xor_sync(0xffffffffu, den.x, o);
        den.y += __shfl_xor_sync(0xffffffffu, den.y, o);
        den.z += __shfl_xor_sync(0xffffffffu, den.z, o);
        den.w += __shfl_xor_sync(0xffffffffu, den.w, o);
    }
    float dh[4] = {den.x, den.y, den.z, den.w};
    float rd = 1.0f / dh[hsel];
    float4 o0 = make_float4(acc[0] * rd, acc[1] * rd, acc[2] * rd, acc[3] * rd);
    float4 o1 = make_float4(acc[4] * rd, acc[5] * rd, acc[6] * rd, acc[7] * rd);
    *(float4*)&orow[0] = o0;
    *(float4*)&orow[4] = o1;
}

// ---------------------------------------------------------------------------
// launch: fork CSR-build chain onto a side stream, overlap with GEMM
// ---------------------------------------------------------------------------
extern "C" void kernel_launch(void* const* d_in, const int* in_sizes, int n_in,
                              void* d_out, int out_size) {
    const float* feat        = (const float*)d_in[0];
    const int*   src         = (const int*)  d_in[1];
    const int*   dst         = (const int*)  d_in[2];
    const int*   edge_feats  = (const int*)  d_in[3];
    const float* fc_w        = (const float*)d_in[4];
    const float* attn_l      = (const float*)d_in[5];
    const float* attn_r      = (const float*)d_in[6];
    const float* edge_weight = (const float*)d_in[7];
    float* out = (float*)d_out;

    static cudaStream_t s_side = nullptr;
    static cudaEvent_t  ev_fork = nullptr, ev_join = nullptr;
    if (s_side == nullptr) {
        cudaStreamCreateWithFlags(&s_side, cudaStreamNonBlocking);
        cudaEventCreateWithFlags(&ev_fork, cudaEventDisableTiming);
        cudaEventCreateWithFlags(&ev_join, cudaEventDisableTiming);
    }

    // fork: CSR chain (depends only on dst) on side stream
    cudaEventRecord(ev_fork, 0);
    cudaStreamWaitEvent(s_side, ev_fork, 0);
    k_hist  <<<(E_EDGES / 4 + 255) / 256, 256, 0, s_side>>>(dst);
    k_scan_a<<<SCAN_NB, 1024, 0, s_side>>>();
    k_scan_c<<<SCAN_NB, 1024, 0, s_side>>>();
    cudaEventRecord(ev_join, s_side);

    // main stream: GEMM (independent of CSR chain)
    dim3 gemm_grid((N_NODES + GBM - 1) / GBM, HD / GBN);   // (391, 2)
    k_gemm<<<gemm_grid, 256>>>(feat, fc_w, attn_l, attn_r);

    // join, then dependent kernels
    cudaStreamWaitEvent(0, ev_join, 0);
    k_build<<<(E_EDGES + 255) / 256, 256>>>(src, dst, edge_feats, edge_weight);
    k_fused<<<(N_NODES + 7) / 8, 256>>>(out);
}

// round 11
// speedup vs baseline: 3.6813x; 1.0045x over previous
#include <cuda_runtime.h>
#include <cuda_fp16.h>
#include <math.h>
#include <stdint.h>

// ---------------------------------------------------------------------------
// Problem constants (fixed by the dataset)
// ---------------------------------------------------------------------------
#define N_NODES 50000
#define E_EDGES 800000
#define IN_F    256
#define H       4
#define D       64
#define HD      256     // H*D
#define ALPHA   100.0f
#define SLOPE_ATTN 0.2f
#define SLOPE_EW   0.01f

#define N4      (N_NODES / 4)        // 12500 int4 groups (N divisible by 4)
#define SCAN_NB ((N4 + 1023) / 1024) // 13 scan blocks

// ---------------------------------------------------------------------------
// Scratch (device globals: no allocation allowed).
// g_deg is zero at module load; k_scan_a re-zeros it after reading, so the
// all-zero invariant holds at the start of every call/replay.
// ---------------------------------------------------------------------------
__device__ __half  g_fth[N_NODES * HD];      // 25.6 MB : projected features (half)
__device__ __align__(16) float g_el[N_NODES * H];
__device__ __align__(16) float g_er[N_NODES * H];
__device__ __align__(16) int   g_deg[N_NODES];
__device__ __align__(16) int   g_off[N_NODES + 4];
__device__ __align__(16) int   g_cur[N_NODES];
__device__ int    g_bsum[SCAN_NB];
__device__ int    g_csrc[E_EDGES];           // CSR: src node per slot
__device__ float4 g_eval[E_EDGES];           // CSR: 4-head logits per slot

__device__ __forceinline__ float lrelu(float x, float s) {
    return x >= 0.0f ? x : s * x;
}
__device__ __forceinline__ uint32_t smem_u32(const void* p) {
    return (uint32_t)__cvta_generic_to_shared(p);
}
__device__ __forceinline__ void ldmatrix_x4(uint32_t& r0, uint32_t& r1,
                                            uint32_t& r2, uint32_t& r3,
                                            uint32_t addr) {
    asm volatile("ldmatrix.sync.aligned.m8n8.x4.shared.b16 {%0,%1,%2,%3}, [%4];"
                 : "=r"(r0), "=r"(r1), "=r"(r2), "=r"(r3) : "r"(addr));
}

// ---------------------------------------------------------------------------
// K1: degree histogram over dst (int4 vectorized; E divisible by 4)
// ---------------------------------------------------------------------------
__global__ __launch_bounds__(256) void k_hist(const int* __restrict__ dst) {
    int i = blockIdx.x * blockDim.x + threadIdx.x;
    if (i >= E_EDGES / 4) return;
    int4 d = ((const int4*)dst)[i];
    atomicAdd(&g_deg[d.x], 1);
    atomicAdd(&g_deg[d.y], 1);
    atomicAdd(&g_deg[d.z], 1);
    atomicAdd(&g_deg[d.w], 1);
}

// ---------------------------------------------------------------------------
// K2a: per-block int4 scan; also re-zeros g_deg for the next call
// ---------------------------------------------------------------------------
__global__ __launch_bounds__(1024) void k_scan_a() {
    __shared__ int wsum[32];
    int tid  = threadIdx.x;
    int lane = tid & 31;
    int w    = tid >> 5;
    int i4   = blockIdx.x * 1024 + tid;

    int4 v = make_int4(0, 0, 0, 0);
    if (i4 < N4) {
        v = ((const int4*)g_deg)[i4];
        ((int4*)g_deg)[i4] = make_int4(0, 0, 0, 0);   // restore invariant
    }
    int tot = v.x + v.y + v.z + v.w;
    int x = tot;
#pragma unroll
    for (int o = 1; o < 32; o <<= 1) {
        int y = __shfl_up_sync(0xffffffffu, x, o);
        if (lane >= o) x += y;
    }
    if (lane == 31) wsum[w] = x;
    __syncthreads();
    if (w == 0) {
        int y = wsum[lane];
#pragma unroll
        for (int o = 1; o < 32; o <<= 1) {
            int z = __shfl_up_sync(0xffffffffu, y, o);
            if (lane >= o) y += z;
        }
        wsum[lane] = y;
    }
    __syncthreads();
    int excl = (w > 0 ? wsum[w - 1] : 0) + x - tot;
    if (i4 < N4)
        ((int4*)g_off)[i4] = make_int4(excl, excl + v.x, excl + v.x + v.y,
                                       excl + v.x + v.y + v.z);
    if (tid == 0) g_bsum[blockIdx.x] = wsum[31];
}

// ---------------------------------------------------------------------------
// K2b: apply block offsets (each block scans the 13 block sums itself),
//      mirror into g_cur
// ---------------------------------------------------------------------------
__global__ __launch_bounds__(1024) void k_scan_c() {
    __shared__ int s_off;
    if (threadIdx.x < 32) {
        int lane = threadIdx.x;
        int v = (lane < SCAN_NB) ? g_bsum[lane] : 0;
        int x = v;
#pragma unroll
        for (int o = 1; o < 32; o <<= 1) {
            int y = __shfl_up_sync(0xffffffffu, x, o);
            if (lane >= o) x += y;
        }
        if (lane == (int)blockIdx.x) s_off = x - v;   // exclusive prefix
    }
    __syncthreads();
    int i4 = blockIdx.x * 1024 + threadIdx.x;
    if (blockIdx.x == 0 && threadIdx.x == 0) g_off[N_NODES] = E_EDGES;
    if (i4 >= N4) return;
    int off = s_off;
    int4 v = ((const int4*)g_off)[i4];
    v.x += off; v.y += off; v.z += off; v.w += off;
    ((int4*)g_off)[i4] = v;
    ((int4*)g_cur)[i4] = v;
}

// ---------------------------------------------------------------------------
// K3: ft = feat @ fc_w^T  (M=50000, N=256, K=256)  fp16 MMA m16n8k16
//     ldmatrix fragment loads + 2 CTAs/SM; epilogue writes half ft + el/er.
// ---------------------------------------------------------------------------
#define GBM 128
#define GBN 128
#define GBK 32
#define KP  20   // half2 row stride: 20 uint32 -> conflict-free LDS/LDSM

__global__ __launch_bounds__(256, 2) void k_gemm(const float* __restrict__ A,
                                                 const float* __restrict__ W,
                                                 const float* __restrict__ attn_l,
                                                 const float* __restrict__ attn_r) {
    __shared__ uint32_t As2[GBM][KP];
    __shared__ uint32_t Bs2[GBN][KP];

    const int bm   = blockIdx.x * GBM;
    const int bn   = blockIdx.y * GBN;
    const int tid  = threadIdx.x;
    const int wid  = tid >> 5;
    const int lane = tid & 31;
    const int wm   = wid & 3;          // 0..3  -> 32 rows each
    const int wn   = wid >> 2;         // 0..1  -> 64 cols each
    const int g    = lane >> 2;        // group id 0..7
    const int t    = lane & 3;         // thread-in-group 0..3

    // ldmatrix base addresses (k-offset added in loop)
    uint32_t a_base[2], b_base[4];
    {
        int arow = lane & 15;
        int acol = (lane >> 4) * 4;                 // uint32 offset within row
#pragma unroll
        for (int i = 0; i < 2; i++)
            a_base[i] = smem_u32(&As2[wm * 32 + i * 16 + arow][acol]);
        int brow = ((lane >> 4) << 3) + (lane & 7);
        int bcol = ((lane >> 3) & 1) * 4;
#pragma unroll
        for (int jp = 0; jp < 4; jp++)
            b_base[jp] = smem_u32(&Bs2[wn * 64 + jp * 16 + brow][bcol]);
    }

    float c[2][8][4];
#pragma unroll
    for (int i = 0; i < 2; i++)
#pragma unroll
        for (int j = 0; j < 8; j++)
#pragma unroll
            for (int q = 0; q < 4; q++) c[i][j][q] = 0.0f;

    for (int k0 = 0; k0 < IN_F; k0 += GBK) {
        // load + convert + store current k-tile
#pragma unroll
        for (int l = 0; l < 4; l++) {
            int fidx = tid + l * 256;      // 0..1023 float4 slots
            int row  = fidx >> 3;          // 0..127
            int col4 = (fidx & 7) * 4;     // float col within tile
            int gr   = bm + row;
            float4 va = make_float4(0.f, 0.f, 0.f, 0.f);
            if (gr < N_NODES) va = *(const float4*)&A[(size_t)gr * IN_F + k0 + col4];
            __half2 a0 = __float22half2_rn(make_float2(va.x, va.y));
            __half2 a1 = __float22half2_rn(make_float2(va.z, va.w));
            *(uint2*)&As2[row][col4 >> 1] =
                make_uint2(*(uint32_t*)&a0, *(uint32_t*)&a1);

            float4 vb = *(const float4*)&W[(size_t)(bn + row) * IN_F + k0 + col4];
            __half2 b0 = __float22half2_rn(make_float2(vb.x, vb.y));
            __half2 b1 = __float22half2_rn(make_float2(vb.z, vb.w));
            *(uint2*)&Bs2[row][col4 >> 1] =
                make_uint2(*(uint32_t*)&b0, *(uint32_t*)&b1);
        }
        __syncthreads();

#pragma unroll
        for (int ks = 0; ks < 2; ks++) {      // two k16 steps per 32-k tile
            const uint32_t koff = ks * 32;    // byte offset (8 uint32)
            uint32_t a[2][4];
#pragma unroll
            for (int i = 0; i < 2; i++)
                ldmatrix_x4(a[i][0], a[i][1], a[i][2], a[i][3], a_base[i] + koff);
            uint32_t b[8][2];
#pragma unroll
            for (int jp = 0; jp < 4; jp++)
                ldmatrix_x4(b[jp * 2][0], b[jp * 2][1],
                            b[jp * 2 + 1][0], b[jp * 2 + 1][1],
                            b_base[jp] + koff);
#pragma unroll
            for (int i = 0; i < 2; i++)
#pragma unroll
                for (int j = 0; j < 8; j++) {
                    asm volatile(
                        "mma.sync.aligned.m16n8k16.row.col.f32.f16.f16.f32 "
                        "{%0,%1,%2,%3},{%4,%5,%6,%7},{%8,%9},{%0,%1,%2,%3};"
                        : "+f"(c[i][j][0]), "+f"(c[i][j][1]),
                          "+f"(c[i][j][2]), "+f"(c[i][j][3])
                        : "r"(a[i][0]), "r"(a[i][1]), "r"(a[i][2]), "r"(a[i][3]),
                          "r"(b[j][0]), "r"(b[j][1]));
                }
        }
        __syncthreads();
    }

    // epilogue: each thread's 16 cols live in exactly one head block of 64
    const int h = (bn + wn * 64) >> 6;                // head index 0..3
    const float* al = attn_l + h * D;
    const float* ar = attn_r + h * D;

#pragma unroll
    for (int i = 0; i < 2; i++) {
        int r0 = bm + wm * 32 + i * 16;
        int ra = r0 + g, rb = r0 + g + 8;
        float ela = 0.f, era = 0.f, elb = 0.f, erb = 0.f;
#pragma unroll
        for (int j = 0; j < 8; j++) {
            int dcol = j * 8 + t * 2;                 // col within head (0..62)
            int col  = bn + wn * 64 + dcol;           // global col
            float a0 = __ldg(&al[dcol]), a1 = __ldg(&al[dcol + 1]);
            float b0 = __ldg(&ar[dcol]), b1 = __ldg(&ar[dcol + 1]);
            ela = fmaf(c[i][j][0], a0, fmaf(c[i][j][1], a1, ela));
            era = fmaf(c[i][j][0], b0, fmaf(c[i][j][1], b1, era));
            elb = fmaf(c[i][j][2], a0, fmaf(c[i][j][3], a1, elb));
            erb = fmaf(c[i][j][2], b0, fmaf(c[i][j][3], b1, erb));
            if (ra < N_NODES)
                *(__half2*)&g_fth[(size_t)ra * HD + col] =
                    __float22half2_rn(make_float2(c[i][j][0], c[i][j][1]));
            if (rb < N_NODES)
                *(__half2*)&g_fth[(size_t)rb * HD + col] =
                    __float22half2_rn(make_float2(c[i][j][2], c[i][j][3]));
        }
        // reduce across the 4 consecutive lanes (t = 0..3) owning this row+head
#pragma unroll
        for (int o = 2; o > 0; o >>= 1) {
            ela += __shfl_down_sync(0xffffffffu, ela, o);
            era += __shfl_down_sync(0xffffffffu, era, o);
            elb += __shfl_down_sync(0xffffffffu, elb, o);
            erb += __shfl_down_sync(0xffffffffu, erb, o);
        }
        if (t == 0) {
            if (ra < N_NODES) { g_el[ra * H + h] = ela; g_er[ra * H + h] = era; }
            if (rb < N_NODES) { g_el[rb * H + h] = elb; g_er[rb * H + h] = erb; }
        }
    }
}

// ---------------------------------------------------------------------------
// K4: per-edge logits + scatter into CSR slots
// ---------------------------------------------------------------------------
__global__ __launch_bounds__(256) void k_build(const int* __restrict__ src,
                                               const int* __restrict__ dst,
                                               const int* __restrict__ etype,
                                               const float* __restrict__ edge_weight) {
    int e = blockIdx.x * blockDim.x + threadIdx.x;
    if (e >= E_EDGES) return;
    int s = src[e], d = dst[e], t = etype[e] - 1;
    float4 elv = *(const float4*)&g_el[s * H];
    float4 erv = *(const float4*)&g_er[d * H];
    float el4[4] = {elv.x, elv.y, elv.z, elv.w};
    float er4[4] = {erv.x, erv.y, erv.z, erv.w};
    float ve[4];
#pragma unroll
    for (int h = 0; h < H; h++) {
        float w = lrelu(__ldg(&edge_weight[t * H + h]) * ALPHA, SLOPE_EW);
        ve[h] = lrelu((el4[h] + er4[h]) * w, SLOPE_ATTN);
    }
    int pos = atomicAdd(&g_cur[d], 1);
    g_csrc[pos] = s;
    g_eval[pos] = make_float4(ve[0], ve[1], ve[2], ve[3]);
}

// ---------------------------------------------------------------------------
// K5: fused edge-softmax + weighted aggregate. One warp per dst node.
// ---------------------------------------------------------------------------
__global__ __launch_bounds__(256) void k_fused(float* __restrict__ out) {
    __shared__ float s_cf[8][32 * 4];     // [warp][edge*4 + head]
    __shared__ int   s_src[8][32];

    int w    = threadIdx.x >> 5;
    int lane = threadIdx.x & 31;
    int n    = blockIdx.x * 8 + w;
    if (n >= N_NODES) return;

    int beg = g_off[n];
    int cnt = g_off[n + 1] - beg;

    float* orow = &out[(size_t)n * HD + lane * 8];
    if (cnt == 0) {
        float4 z = make_float4(0.f, 0.f, 0.f, 0.f);
        *(float4*)&orow[0] = z;
        *(float4*)&orow[4] = z;
        return;
    }

    // pass 1: per-head max
    float4 mx = make_float4(-INFINITY, -INFINITY, -INFINITY, -INFINITY);
    for (int i = lane; i < cnt; i += 32) {
        float4 v = g_eval[beg + i];
        mx.x = fmaxf(mx.x, v.x); mx.y = fmaxf(mx.y, v.y);
        mx.z = fmaxf(mx.z, v.z); mx.w = fmaxf(mx.w, v.w);
    }
#pragma unroll
    for (int o = 16; o > 0; o >>= 1) {
        mx.x = fmaxf(mx.x, __shfl_xor_sync(0xffffffffu, mx.x, o));
        mx.y = fmaxf(mx.y, __shfl_xor_sync(0xffffffffu, mx.y, o));
        mx.z = fmaxf(mx.z, __shfl_xor_sync(0xffffffffu, mx.z, o));
        mx.w = fmaxf(mx.w, __shfl_xor_sync(0xffffffffu, mx.w, o));
    }

    // pass 2: exp coefficients + denominator + register-accumulated aggregate
    const int hsel = lane >> 3;
    const uint4* __restrict__ fth = (const uint4*)g_fth;   // 32 uint4 per node

    float acc[8];
#pragma unroll
    for (int q = 0; q < 8; q++) acc[q] = 0.0f;
    float4 den = make_float4(0.f, 0.f, 0.f, 0.f);

    for (int base = 0; base < cnt; base += 32) {
        int i = base + lane;
        int m = min(32, cnt - base);
        if (i < cnt) {
            float4 v = g_eval[beg + i];
            float4 cf;
            cf.x = __expf(v.x - mx.x);
            cf.y = __expf(v.y - mx.y);
            cf.z = __expf(v.z - mx.z);
            cf.w = __expf(v.w - mx.w);
            den.x += cf.x; den.y += cf.y; den.z += cf.z; den.w += cf.w;
            s_cf[w][lane * 4 + 0] = cf.x;
            s_cf[w][lane * 4 + 1] = cf.y;
            s_cf[w][lane * 4 + 2] = cf.z;
            s_cf[w][lane * 4 + 3] = cf.w;
            s_src[w][lane] = g_csrc[beg + i];
        }
        __syncwarp();
#pragma unroll 4
        for (int j = 0; j < m; j++) {
            int   sidx = s_src[w][j];
            float cf   = s_cf[w][j * 4 + hsel];
            uint4 hv   = __ldg(&fth[(size_t)sidx * 32 + lane]);
            const __half2* hp = (const __half2*)&hv;
#pragma unroll
            for (int p = 0; p < 4; p++) {
                float2 f2 = __half22float2(hp[p]);
                acc[2 * p + 0] = fmaf(cf, f2.x, acc[2 * p + 0]);
                acc[2 * p + 1] = fmaf(cf, f2.y, acc[2 * p + 1]);
            }
        }
        __syncwarp();
    }

    // reduce denominator across warp, normalize, write row once
#pragma unroll
    for (int o = 16; o > 0; o >>= 1) {
        den.x += __shfl_xor_sync(0xffffffffu, den.x, o);
        den.y += __shfl_xor_sync(0xffffffffu, den.y, o);
        den.z += __shfl_xor_sync(0xffffffffu, den.z, o);
        den.w += __shfl_xor_sync(0xffffffffu, den.w, o);
    }
    float dh[4] = {den.x, den.y, den.z, den.w};
    float rd = 1.0f / dh[hsel];
    float4 o0 = make_float4(acc[0] * rd, acc[1] * rd, acc[2] * rd, acc[3] * rd);
    float4 o1 = make_float4(acc[4] * rd, acc[5] * rd, acc[6] * rd, acc[7] * rd);
    *(float4*)&orow[0] = o0;
    *(float4*)&orow[4] = o1;
}

// ---------------------------------------------------------------------------
// launch: fork CSR-build chain onto a side stream, overlap with GEMM
// ---------------------------------------------------------------------------
extern "C" void kernel_launch(void* const* d_in, const int* in_sizes, int n_in,
                              void* d_out, int out_size) {
    const float* feat        = (const float*)d_in[0];
    const int*   src         = (const int*)  d_in[1];
    const int*   dst         = (const int*)  d_in[2];
    const int*   edge_feats  = (const int*)  d_in[3];
    const float* fc_w        = (const float*)d_in[4];
    const float* attn_l      = (const float*)d_in[5];
    const float* attn_r      = (const float*)d_in[6];
    const float* edge_weight = (const float*)d_in[7];
    float* out = (float*)d_out;

    static cudaStream_t s_side = nullptr;
    static cudaEvent_t  ev_fork = nullptr, ev_join = nullptr;
    if (s_side == nullptr) {
        cudaStreamCreateWithFlags(&s_side, cudaStreamNonBlocking);
        cudaEventCreateWithFlags(&ev_fork, cudaEventDisableTiming);
        cudaEventCreateWithFlags(&ev_join, cudaEventDisableTiming);
    }

    // fork: CSR chain (depends only on dst) on side stream
    cudaEventRecord(ev_fork, 0);
    cudaStreamWaitEvent(s_side, ev_fork, 0);
    k_hist  <<<(E_EDGES / 4 + 255) / 256, 256, 0, s_side>>>(dst);
    k_scan_a<<<SCAN_NB, 1024, 0, s_side>>>();
    k_scan_c<<<SCAN_NB, 1024, 0, s_side>>>();
    cudaEventRecord(ev_join, s_side);

    // main stream: GEMM (independent of CSR chain)
    dim3 gemm_grid((N_NODES + GBM - 1) / GBM, HD / GBN);   // (391, 2)
    k_gemm<<<gemm_grid, 256>>>(feat, fc_w, attn_l, attn_r);

    // join, then dependent kernels
    cudaStreamWaitEvent(0, ev_join, 0);
    k_build<<<(E_EDGES + 255) / 256, 256>>>(src, dst, edge_feats, edge_weight);
    k_fused<<<(N_NODES + 7) / 8, 256>>>(out);
}